// round 9
// baseline (speedup 1.0000x reference)
#include <cuda_runtime.h>
#include <cuda_bf16.h>
#include <math.h>
#include <stdint.h>

// Problem constants
#define BATCH 2
#define SEQ   2048
#define DIM   1024
#define HEADS 16
#define HD    64
#define QKVD  3072   // 3*DIM

// ---------------------------------------------------------------------------
// Global scratch (alloc-free rule). All bf16 hi/lo pairs represent fp32.
// ---------------------------------------------------------------------------
__device__ __nv_bfloat16 g_xh [(size_t)BATCH * SEQ * DIM];
__device__ __nv_bfloat16 g_xl [(size_t)BATCH * SEQ * DIM];
__device__ __nv_bfloat16 g_wqh[(size_t)QKVD * DIM];
__device__ __nv_bfloat16 g_wql[(size_t)QKVD * DIM];
__device__ __nv_bfloat16 g_woh[(size_t)DIM * DIM];
__device__ __nv_bfloat16 g_wol[(size_t)DIM * DIM];
__device__ __nv_bfloat16 g_qkvh[(size_t)BATCH * SEQ * QKVD];
__device__ __nv_bfloat16 g_qkvl[(size_t)BATCH * SEQ * QKVD];
__device__ __nv_bfloat16 g_aoh[(size_t)BATCH * SEQ * DIM];
__device__ __nv_bfloat16 g_aol[(size_t)BATCH * SEQ * DIM];

// ============================================================================
// Helpers (generic PTX, compute_103-safe)
// ============================================================================
__device__ __forceinline__ uint32_t smem_u32(const void* p) {
    uint32_t a;
    asm("{ .reg .u64 t; cvta.to.shared.u64 t, %1; cvt.u32.u64 %0, t; }"
        : "=r"(a) : "l"(p));
    return a;
}
__device__ __forceinline__ void ldsm_x4(uint32_t& r0, uint32_t& r1,
                                        uint32_t& r2, uint32_t& r3,
                                        uint32_t addr) {
    asm volatile("ldmatrix.sync.aligned.m8n8.x4.shared.b16 {%0,%1,%2,%3}, [%4];"
                 : "=r"(r0), "=r"(r1), "=r"(r2), "=r"(r3) : "r"(addr));
}
__device__ __forceinline__ void mma_bf16(float* d, const uint32_t* a,
                                         const uint32_t* b) {
    asm volatile(
        "mma.sync.aligned.m16n8k16.row.col.f32.bf16.bf16.f32 "
        "{%0,%1,%2,%3}, {%4,%5,%6,%7}, {%8,%9}, {%0,%1,%2,%3};"
        : "+f"(d[0]), "+f"(d[1]), "+f"(d[2]), "+f"(d[3])
        : "r"(a[0]), "r"(a[1]), "r"(a[2]), "r"(a[3]), "r"(b[0]), "r"(b[1]));
}
__device__ __forceinline__ void split2(float x, float y,
                                       uint32_t& hi, uint32_t& lo) {
    __nv_bfloat162 h = __floats2bfloat162_rn(x, y);
    float rx = x - __bfloat162float(__low2bfloat16(h));
    float ry = y - __bfloat162float(__high2bfloat16(h));
    __nv_bfloat162 l = __floats2bfloat162_rn(rx, ry);
    hi = *(uint32_t*)&h;
    lo = *(uint32_t*)&l;
}
__device__ __forceinline__ void cp16(uint32_t smem, const void* gmem) {
    asm volatile("cp.async.cg.shared.global [%0], [%1], 16;"
                 :: "r"(smem), "l"(gmem));
}
#define CP_COMMIT() asm volatile("cp.async.commit_group;" ::: "memory")
#define CP_WAIT(n)  asm volatile("cp.async.wait_group %0;" :: "n"(n) : "memory")

// ============================================================================
// split_arr: fp32 -> (bf16 hi, bf16 lo), grid-stride over float4
// ============================================================================
__global__ void split_arr(const float* __restrict__ src,
                          __nv_bfloat16* __restrict__ hi,
                          __nv_bfloat16* __restrict__ lo, int n4) {
    for (int i = blockIdx.x * blockDim.x + threadIdx.x; i < n4;
         i += gridDim.x * blockDim.x) {
        float4 v = ((const float4*)src)[i];
        uint2 h, l;
        split2(v.x, v.y, h.x, l.x);
        split2(v.z, v.w, h.y, l.y);
        ((uint2*)hi)[i] = h;
        ((uint2*)lo)[i] = l;
    }
}

// ============================================================================
// bf16x3 GEMM, pre-split inputs:  C = A @ B^T + bias
// CTA tile 256x128, K-chunk 64, 2-stage cp.async, 8 warps (4m x 2n),
// warp tile 64x64. MMAs issued in 3 product passes (hh, hl, lh) so
// same-accumulator reuse is 32 MMAs apart (no RAW stall on HMMA latency).
// ============================================================================
#define GKC    64
#define GPITCH 72
#define GA_TILE (256 * GPITCH * 2)
#define GB_TILE (128 * GPITCH * 2)
#define GSTAGE_B (2 * GA_TILE + 2 * GB_TILE)
#define G_SMEM_BYTES (2 * GSTAGE_B)

__global__ __launch_bounds__(256, 1) void gemm_bf16(
    int M, int N_, int K,
    const __nv_bfloat16* __restrict__ Ah, const __nv_bfloat16* __restrict__ Al,
    const __nv_bfloat16* __restrict__ Bh, const __nv_bfloat16* __restrict__ Bl,
    const float* __restrict__ bias,
    float* __restrict__ C,
    __nv_bfloat16* __restrict__ Ch, __nv_bfloat16* __restrict__ Cl)
{
    extern __shared__ __align__(16) char sm[];
    const uint32_t sb0 = smem_u32(sm);

    const int tid = threadIdx.x;
    const int wid = tid >> 5;
    const int lane = tid & 31;
    const int n0 = blockIdx.x * 128;
    const int m0 = blockIdx.y * 256;
    const int warp_m = wid & 3;
    const int warp_n = wid >> 2;

    float acc[4][8][4];
#pragma unroll
    for (int mt = 0; mt < 4; mt++)
#pragma unroll
        for (int nt = 0; nt < 8; nt++)
#pragma unroll
            for (int r = 0; r < 4; r++) acc[mt][nt][r] = 0.0f;

    const int a_row = warp_m * 64 + (lane & 7) + ((lane >> 3) & 1) * 8;
    const int a_kof = ((lane >> 4) & 1) * 8;
    const int b_row = warp_n * 64 + (lane & 7) + ((lane >> 4) & 1) * 8;
    const int b_kof = ((lane >> 3) & 1) * 8;

    const int nchunk = K / GKC;

    auto issue_chunk = [&](int ic, int s) {
        const uint32_t sb = sb0 + (uint32_t)s * GSTAGE_B;
        const int kc = ic * GKC;
#pragma unroll
        for (int i = 0; i < 8; i++) {
            const int id = tid + 256 * i;
            const int row = id >> 3;
            const int c8 = (id & 7) * 8;
            const uint32_t so = (uint32_t)(row * GPITCH + c8) * 2;
            const size_t ga = (size_t)(m0 + row) * K + kc + c8;
            cp16(sb + so,           Ah + ga);
            cp16(sb + GA_TILE + so, Al + ga);
        }
#pragma unroll
        for (int i = 0; i < 4; i++) {
            const int id = tid + 256 * i;
            const int row = id >> 3;
            const int c8 = (id & 7) * 8;
            const uint32_t so = (uint32_t)(row * GPITCH + c8) * 2;
            const size_t gb = (size_t)(n0 + row) * K + kc + c8;
            cp16(sb + 2 * GA_TILE + so,           Bh + gb);
            cp16(sb + 2 * GA_TILE + GB_TILE + so, Bl + gb);
        }
    };

    issue_chunk(0, 0); CP_COMMIT();

    for (int ic = 0; ic < nchunk; ic++) {
        if (ic + 1 < nchunk) {
            issue_chunk(ic + 1, (ic + 1) & 1); CP_COMMIT();
            CP_WAIT(1);
        } else {
            CP_WAIT(0);
        }
        __syncthreads();

        const uint32_t sb  = sb0 + (uint32_t)(ic & 1) * GSTAGE_B;
        const uint32_t sAh = sb;
        const uint32_t sAl = sb + GA_TILE;
        const uint32_t sBh = sb + 2 * GA_TILE;
        const uint32_t sBl = sb + 2 * GA_TILE + GB_TILE;

#pragma unroll
        for (int ks = 0; ks < 4; ks++) {
            const int k16 = ks * 16;
            uint32_t ah[4][4], al[4][4];
#pragma unroll
            for (int mt = 0; mt < 4; mt++) {
                const uint32_t aoff =
                    (uint32_t)((a_row + mt * 16) * GPITCH + k16 + a_kof) * 2;
                ldsm_x4(ah[mt][0], ah[mt][1], ah[mt][2], ah[mt][3], sAh + aoff);
                ldsm_x4(al[mt][0], al[mt][1], al[mt][2], al[mt][3], sAl + aoff);
            }
            uint32_t bh[8][2], bl[8][2];
#pragma unroll
            for (int ntp = 0; ntp < 4; ntp++) {
                const uint32_t boff =
                    (uint32_t)((b_row + ntp * 16) * GPITCH + k16 + b_kof) * 2;
                ldsm_x4(bh[2 * ntp][0], bh[2 * ntp][1],
                        bh[2 * ntp + 1][0], bh[2 * ntp + 1][1], sBh + boff);
                ldsm_x4(bl[2 * ntp][0], bl[2 * ntp][1],
                        bl[2 * ntp + 1][0], bl[2 * ntp + 1][1], sBl + boff);
            }
            // Product-pass order: all hh, then all hl, then all lh.
#pragma unroll
            for (int mt = 0; mt < 4; mt++)
#pragma unroll
                for (int nt = 0; nt < 8; nt++)
                    mma_bf16(acc[mt][nt], ah[mt], bh[nt]);
#pragma unroll
            for (int mt = 0; mt < 4; mt++)
#pragma unroll
                for (int nt = 0; nt < 8; nt++)
                    mma_bf16(acc[mt][nt], ah[mt], bl[nt]);
#pragma unroll
            for (int mt = 0; mt < 4; mt++)
#pragma unroll
                for (int nt = 0; nt < 8; nt++)
                    mma_bf16(acc[mt][nt], al[mt], bh[nt]);
        }
        __syncthreads();
    }

    // Epilogue
    const int er0 = m0 + warp_m * 64 + (lane >> 2);
    const int ec0 = n0 + warp_n * 64 + (lane & 3) * 2;
#pragma unroll
    for (int mt = 0; mt < 4; mt++) {
#pragma unroll
        for (int nt = 0; nt < 8; nt++) {
            const int col = ec0 + nt * 8;
            const float bx = bias[col], by = bias[col + 1];
            const size_t o0 = (size_t)(er0 + mt * 16) * N_ + col;
            const size_t o1 = (size_t)(er0 + mt * 16 + 8) * N_ + col;
            const float c00 = acc[mt][nt][0] + bx, c01 = acc[mt][nt][1] + by;
            const float c10 = acc[mt][nt][2] + bx, c11 = acc[mt][nt][3] + by;
            if (C) {
                *(float2*)(C + o0) = make_float2(c00, c01);
                *(float2*)(C + o1) = make_float2(c10, c11);
            } else {
                uint32_t h0, l0w, h1, l1w;
                split2(c00, c01, h0, l0w);
                split2(c10, c11, h1, l1w);
                *(uint32_t*)(Ch + o0) = h0;  *(uint32_t*)(Cl + o0) = l0w;
                *(uint32_t*)(Ch + o1) = h1;  *(uint32_t*)(Cl + o1) = l1w;
            }
        }
    }
}

// ============================================================================
// Flash attention, tensor cores, pre-split bf16 qkv inputs.
// Same product-pass MMA reordering as gemm.
// ============================================================================
#define APITCH 72
#define A_QTILE (128 * APITCH * 2)
#define A_KTILE (64 * APITCH * 2)
#define A_SMEM_BYTES (2 * A_QTILE + 4 * A_KTILE)   // 73728

__global__ __launch_bounds__(256, 1) void attn_tc(
    const __nv_bfloat16* __restrict__ qkvh,
    const __nv_bfloat16* __restrict__ qkvl,
    __nv_bfloat16* __restrict__ aoh,
    __nv_bfloat16* __restrict__ aol)
{
    extern __shared__ __align__(16) char smema[];
    const uint32_t sQh  = smem_u32(smema);
    const uint32_t sQl  = sQh + A_QTILE;
    const uint32_t sKh  = sQl + A_QTILE;
    const uint32_t sKl  = sKh + A_KTILE;
    const uint32_t sVth = sKl + A_KTILE;
    const uint32_t sVtl = sVth + A_KTILE;
    __nv_bfloat16* pVth = (__nv_bfloat16*)(smema + 2 * A_QTILE + 2 * A_KTILE);
    __nv_bfloat16* pVtl = (__nv_bfloat16*)(smema + 2 * A_QTILE + 3 * A_KTILE);

    const int qt = gridDim.x - 1 - blockIdx.x;
    const int h  = blockIdx.y;
    const int b  = blockIdx.z;
    const int tid = threadIdx.x;
    const int wid = tid >> 5;
    const int lane = tid & 31;

    const size_t bN = (size_t)b * SEQ;
    const int qcol = h * HD;
    const int kcol = DIM + h * HD;
    const int vcol = 2 * DIM + h * HD;

#pragma unroll
    for (int i = 0; i < 4; i++) {
        const int id = tid + 256 * i;
        const int row = id >> 3;
        const int c8 = (id & 7) * 8;
        const uint32_t so = (uint32_t)(row * APITCH + c8) * 2;
        const size_t g = (bN + qt * 128 + row) * QKVD + qcol + c8;
        cp16(sQh + so, qkvh + g);
        cp16(sQl + so, qkvl + g);
    }
    CP_COMMIT();
    CP_WAIT(0);
    __syncthreads();

    const int a_row = wid * 16 + (lane & 7) + ((lane >> 3) & 1) * 8;
    const int a_kof = ((lane >> 4) & 1) * 8;
    uint32_t qh[4][4], ql[4][4];
#pragma unroll
    for (int ks = 0; ks < 4; ks++) {
        const uint32_t off = (uint32_t)(a_row * APITCH + ks * 16 + a_kof) * 2;
        ldsm_x4(qh[ks][0], qh[ks][1], qh[ks][2], qh[ks][3], sQh + off);
        ldsm_x4(ql[ks][0], ql[ks][1], ql[ks][2], ql[ks][3], sQl + off);
    }
    __syncthreads();

    const int b_row = (lane & 7) + ((lane >> 4) & 1) * 8;
    const int b_kof = ((lane >> 3) & 1) * 8;

    float o[8][4];
#pragma unroll
    for (int nt = 0; nt < 8; nt++)
#pragma unroll
        for (int r = 0; r < 4; r++) o[nt][r] = 0.0f;
    float m0 = -1e30f, m1 = -1e30f, l0 = 0.0f, l1 = 0.0f;

    const float scale = 0.125f;
    const int row_lo = qt * 128 + wid * 16 + (lane >> 2);
    const int row_hi = row_lo + 8;
    const int ntiles = (qt + 1) * 2;

    const int vrr = tid >> 2;
    const int vd0 = (tid & 3) * 16;

    for (int kt = 0; kt < ntiles; kt++) {
        const int kb = kt * 64;

#pragma unroll
        for (int i = 0; i < 2; i++) {
            const int id = tid + 256 * i;
            const int row = id >> 3;
            const int c8 = (id & 7) * 8;
            const uint32_t so = (uint32_t)(row * APITCH + c8) * 2;
            const size_t g = (bN + kb + row) * QKVD + kcol + c8;
            cp16(sKh + so, qkvh + g);
            cp16(sKl + so, qkvl + g);
        }
        {
            const size_t g = (bN + kb + vrr) * QKVD + vcol + vd0;
            union { uint4 q; __nv_bfloat16 e[8]; } uh0, uh1, ul0, ul1;
            uh0.q = *(const uint4*)(qkvh + g);
            uh1.q = *(const uint4*)(qkvh + g + 8);
            ul0.q = *(const uint4*)(qkvl + g);
            ul1.q = *(const uint4*)(qkvl + g + 8);
#pragma unroll
            for (int e = 0; e < 8; e++) {
                pVth[(vd0 + e) * APITCH + vrr]     = uh0.e[e];
                pVth[(vd0 + 8 + e) * APITCH + vrr] = uh1.e[e];
                pVtl[(vd0 + e) * APITCH + vrr]     = ul0.e[e];
                pVtl[(vd0 + 8 + e) * APITCH + vrr] = ul1.e[e];
            }
        }
        CP_COMMIT();
        CP_WAIT(0);
        __syncthreads();

        float s[8][4];
#pragma unroll
        for (int nt = 0; nt < 8; nt++)
#pragma unroll
            for (int r = 0; r < 4; r++) s[nt][r] = 0.0f;

#pragma unroll
        for (int ks = 0; ks < 4; ks++) {
            uint32_t kh[8][2], kl[8][2];
#pragma unroll
            for (int ntp = 0; ntp < 4; ntp++) {
                const uint32_t off =
                    (uint32_t)((ntp * 16 + b_row) * APITCH + ks * 16 + b_kof) * 2;
                ldsm_x4(kh[2 * ntp][0], kh[2 * ntp][1],
                        kh[2 * ntp + 1][0], kh[2 * ntp + 1][1], sKh + off);
                ldsm_x4(kl[2 * ntp][0], kl[2 * ntp][1],
                        kl[2 * ntp + 1][0], kl[2 * ntp + 1][1], sKl + off);
            }
            // Product-pass order (same-acc reuse 8 apart)
#pragma unroll
            for (int nt = 0; nt < 8; nt++) mma_bf16(s[nt], qh[ks], kh[nt]);
#pragma unroll
            for (int nt = 0; nt < 8; nt++) mma_bf16(s[nt], qh[ks], kl[nt]);
#pragma unroll
            for (int nt = 0; nt < 8; nt++) mma_bf16(s[nt], ql[ks], kh[nt]);
        }

        const bool full = (kb + 63) <= qt * 128;
        if (full) {
#pragma unroll
            for (int nt = 0; nt < 8; nt++)
#pragma unroll
                for (int r = 0; r < 4; r++) s[nt][r] *= scale;
        } else {
#pragma unroll
            for (int nt = 0; nt < 8; nt++) {
                const int col = kb + nt * 8 + (lane & 3) * 2;
                s[nt][0] = (col     <= row_lo) ? s[nt][0] * scale : -1e30f;
                s[nt][1] = (col + 1 <= row_lo) ? s[nt][1] * scale : -1e30f;
                s[nt][2] = (col     <= row_hi) ? s[nt][2] * scale : -1e30f;
                s[nt][3] = (col + 1 <= row_hi) ? s[nt][3] * scale : -1e30f;
            }
        }

        float tm0 = -1e30f, tm1 = -1e30f;
#pragma unroll
        for (int nt = 0; nt < 8; nt++) {
            tm0 = fmaxf(tm0, fmaxf(s[nt][0], s[nt][1]));
            tm1 = fmaxf(tm1, fmaxf(s[nt][2], s[nt][3]));
        }
        tm0 = fmaxf(tm0, __shfl_xor_sync(0xffffffffu, tm0, 1));
        tm0 = fmaxf(tm0, __shfl_xor_sync(0xffffffffu, tm0, 2));
        tm1 = fmaxf(tm1, __shfl_xor_sync(0xffffffffu, tm1, 1));
        tm1 = fmaxf(tm1, __shfl_xor_sync(0xffffffffu, tm1, 2));

        const float nm0 = fmaxf(m0, tm0);
        const float nm1 = fmaxf(m1, tm1);
        const float corr0 = __expf(m0 - nm0);
        const float corr1 = __expf(m1 - nm1);

        float ps0 = 0.0f, ps1 = 0.0f;
#pragma unroll
        for (int nt = 0; nt < 8; nt++) {
            s[nt][0] = __expf(s[nt][0] - nm0); ps0 += s[nt][0];
            s[nt][1] = __expf(s[nt][1] - nm0); ps0 += s[nt][1];
            s[nt][2] = __expf(s[nt][2] - nm1); ps1 += s[nt][2];
            s[nt][3] = __expf(s[nt][3] - nm1); ps1 += s[nt][3];
        }
        ps0 += __shfl_xor_sync(0xffffffffu, ps0, 1);
        ps0 += __shfl_xor_sync(0xffffffffu, ps0, 2);
        ps1 += __shfl_xor_sync(0xffffffffu, ps1, 1);
        ps1 += __shfl_xor_sync(0xffffffffu, ps1, 2);

        l0 = l0 * corr0 + ps0; m0 = nm0;
        l1 = l1 * corr1 + ps1; m1 = nm1;
#pragma unroll
        for (int nt = 0; nt < 8; nt++) {
            o[nt][0] *= corr0; o[nt][1] *= corr0;
            o[nt][2] *= corr1; o[nt][3] *= corr1;
        }

        // P repack + V fragments for all 4 k-steps first, then 3 passes.
        uint32_t pah[4][4], pal[4][4], vh[4][8][2], vl[4][8][2];
#pragma unroll
        for (int ks = 0; ks < 4; ks++) {
            const int j = 2 * ks;
            split2(s[j][0],     s[j][1],     pah[ks][0], pal[ks][0]);
            split2(s[j][2],     s[j][3],     pah[ks][1], pal[ks][1]);
            split2(s[j + 1][0], s[j + 1][1], pah[ks][2], pal[ks][2]);
            split2(s[j + 1][2], s[j + 1][3], pah[ks][3], pal[ks][3]);
#pragma unroll
            for (int ntp = 0; ntp < 4; ntp++) {
                const uint32_t off =
                    (uint32_t)((ntp * 16 + b_row) * APITCH + ks * 16 + b_kof) * 2;
                ldsm_x4(vh[ks][2 * ntp][0], vh[ks][2 * ntp][1],
                        vh[ks][2 * ntp + 1][0], vh[ks][2 * ntp + 1][1], sVth + off);
                ldsm_x4(vl[ks][2 * ntp][0], vl[ks][2 * ntp][1],
                        vl[ks][2 * ntp + 1][0], vl[ks][2 * ntp + 1][1], sVtl + off);
            }
        }
#pragma unroll
        for (int ks = 0; ks < 4; ks++)
#pragma unroll
            for (int nt = 0; nt < 8; nt++) mma_bf16(o[nt], pah[ks], vh[ks][nt]);
#pragma unroll
        for (int ks = 0; ks < 4; ks++)
#pragma unroll
            for (int nt = 0; nt < 8; nt++) mma_bf16(o[nt], pah[ks], vl[ks][nt]);
#pragma unroll
        for (int ks = 0; ks < 4; ks++)
#pragma unroll
            for (int nt = 0; nt < 8; nt++) mma_bf16(o[nt], pal[ks], vh[ks][nt]);
        __syncthreads();
    }

    const float inv0 = 1.0f / l0;
    const float inv1 = 1.0f / l1;
#pragma unroll
    for (int nt = 0; nt < 8; nt++) {
        const int col = h * HD + nt * 8 + (lane & 3) * 2;
        const size_t o0 = (bN + row_lo) * DIM + col;
        const size_t o1 = (bN + row_hi) * DIM + col;
        uint32_t h0, l0w, h1, l1w;
        split2(o[nt][0] * inv0, o[nt][1] * inv0, h0, l0w);
        split2(o[nt][2] * inv1, o[nt][3] * inv1, h1, l1w);
        *(uint32_t*)(aoh + o0) = h0;  *(uint32_t*)(aol + o0) = l0w;
        *(uint32_t*)(aoh + o1) = h1;  *(uint32_t*)(aol + o1) = l1w;
    }
}

// ---------------------------------------------------------------------------
extern "C" void kernel_launch(void* const* d_in, const int* in_sizes, int n_in,
                              void* d_out, int out_size)
{
    const float* x     = (const float*)d_in[0];
    const float* W_qkv = (const float*)d_in[1];
    const float* b_qkv = (const float*)d_in[2];
    const float* W_out = (const float*)d_in[3];
    const float* b_out = (const float*)d_in[4];
    float* out = (float*)d_out;

    __nv_bfloat16 *xh, *xl, *wqh, *wql, *woh, *wol, *qkvh, *qkvl, *aoh, *aol;
    cudaGetSymbolAddress((void**)&xh,  g_xh);   cudaGetSymbolAddress((void**)&xl,  g_xl);
    cudaGetSymbolAddress((void**)&wqh, g_wqh);  cudaGetSymbolAddress((void**)&wql, g_wql);
    cudaGetSymbolAddress((void**)&woh, g_woh);  cudaGetSymbolAddress((void**)&wol, g_wol);
    cudaGetSymbolAddress((void**)&qkvh, g_qkvh); cudaGetSymbolAddress((void**)&qkvl, g_qkvl);
    cudaGetSymbolAddress((void**)&aoh, g_aoh);  cudaGetSymbolAddress((void**)&aol, g_aol);

    cudaFuncSetAttribute(gemm_bf16,
                         cudaFuncAttributeMaxDynamicSharedMemorySize, G_SMEM_BYTES);
    cudaFuncSetAttribute(attn_tc,
                         cudaFuncAttributeMaxDynamicSharedMemorySize, A_SMEM_BYTES);

    const int M = BATCH * SEQ;  // 4096

    // 0) Pre-split inputs
    split_arr<<<1024, 256>>>(x,     xh,  xl,  M * DIM / 4);
    split_arr<<<1024, 256>>>(W_qkv, wqh, wql, QKVD * DIM / 4);
    split_arr<<<512,  256>>>(W_out, woh, wol, DIM * DIM / 4);

    // 1) QKV projection -> split bf16 qkv
    {
        dim3 grid(QKVD / 128, M / 256);
        gemm_bf16<<<grid, 256, G_SMEM_BYTES>>>(M, QKVD, DIM, xh, xl, wqh, wql,
                                               b_qkv, nullptr, qkvh, qkvl);
    }
    // 2) Attention -> split bf16 aout
    {
        dim3 grid(SEQ / 128, HEADS, BATCH);
        attn_tc<<<grid, 256, A_SMEM_BYTES>>>(qkvh, qkvl, aoh, aol);
    }
    // 3) Output projection -> fp32 out
    {
        dim3 grid(DIM / 128, M / 256);
        gemm_bf16<<<grid, 256, G_SMEM_BYTES>>>(M, DIM, DIM, aoh, aol, woh, wol,
                                               b_out, out, nullptr, nullptr);
    }
}

// round 10
// speedup vs baseline: 1.3878x; 1.3878x over previous
#include <cuda_runtime.h>
#include <cuda_fp16.h>
#include <math.h>
#include <stdint.h>

// Problem constants
#define BATCH 2
#define SEQ   2048
#define DIM   1024
#define HEADS 16
#define HD    64
#define QKVD  3072   // 3*DIM

// ---------------------------------------------------------------------------
// Global scratch (alloc-free rule). hi/lo fp16 pairs represent fp32 (A-side);
// B-side operands are single fp16 (one rounding, 2^-12 rel).
// ---------------------------------------------------------------------------
__device__ __half g_xh [(size_t)BATCH * SEQ * DIM];
__device__ __half g_xl [(size_t)BATCH * SEQ * DIM];
__device__ __half g_wqh[(size_t)QKVD * DIM];
__device__ __half g_woh[(size_t)DIM * DIM];
__device__ __half g_qkvh[(size_t)BATCH * SEQ * QKVD];
__device__ __half g_qkvl[(size_t)BATCH * SEQ * QKVD];
__device__ __half g_aoh[(size_t)BATCH * SEQ * DIM];
__device__ __half g_aol[(size_t)BATCH * SEQ * DIM];

// ============================================================================
// Helpers (generic PTX, compute_103-safe)
// ============================================================================
__device__ __forceinline__ uint32_t smem_u32(const void* p) {
    uint32_t a;
    asm("{ .reg .u64 t; cvta.to.shared.u64 t, %1; cvt.u32.u64 %0, t; }"
        : "=r"(a) : "l"(p));
    return a;
}
__device__ __forceinline__ void ldsm_x4(uint32_t& r0, uint32_t& r1,
                                        uint32_t& r2, uint32_t& r3,
                                        uint32_t addr) {
    asm volatile("ldmatrix.sync.aligned.m8n8.x4.shared.b16 {%0,%1,%2,%3}, [%4];"
                 : "=r"(r0), "=r"(r1), "=r"(r2), "=r"(r3) : "r"(addr));
}
__device__ __forceinline__ void mma_f16(float* d, const uint32_t* a,
                                        const uint32_t* b) {
    asm volatile(
        "mma.sync.aligned.m16n8k16.row.col.f32.f16.f16.f32 "
        "{%0,%1,%2,%3}, {%4,%5,%6,%7}, {%8,%9}, {%0,%1,%2,%3};"
        : "+f"(d[0]), "+f"(d[1]), "+f"(d[2]), "+f"(d[3])
        : "r"(a[0]), "r"(a[1]), "r"(a[2]), "r"(a[3]), "r"(b[0]), "r"(b[1]));
}
// fp32 pair -> fp16 hi + fp16 lo (residual), packed as half2 words
__device__ __forceinline__ void split2h(float x, float y,
                                        uint32_t& hi, uint32_t& lo) {
    __half2 h = __floats2half2_rn(x, y);
    float rx = x - __half2float(__low2half(h));
    float ry = y - __half2float(__high2half(h));
    __half2 l = __floats2half2_rn(rx, ry);
    hi = *(uint32_t*)&h;
    lo = *(uint32_t*)&l;
}
__device__ __forceinline__ void cp16(uint32_t smem, const void* gmem) {
    asm volatile("cp.async.cg.shared.global [%0], [%1], 16;"
                 :: "r"(smem), "l"(gmem));
}
#define CP_COMMIT() asm volatile("cp.async.commit_group;" ::: "memory")
#define CP_WAIT(n)  asm volatile("cp.async.wait_group %0;" :: "n"(n) : "memory")

// ============================================================================
// split_arr: fp32 -> (fp16 hi, fp16 lo).   round_arr: fp32 -> fp16.
// ============================================================================
__global__ void split_arr(const float* __restrict__ src,
                          __half* __restrict__ hi,
                          __half* __restrict__ lo, int n4) {
    for (int i = blockIdx.x * blockDim.x + threadIdx.x; i < n4;
         i += gridDim.x * blockDim.x) {
        float4 v = ((const float4*)src)[i];
        uint2 h, l;
        split2h(v.x, v.y, h.x, l.x);
        split2h(v.z, v.w, h.y, l.y);
        ((uint2*)hi)[i] = h;
        ((uint2*)lo)[i] = l;
    }
}
__global__ void round_arr(const float* __restrict__ src,
                          __half* __restrict__ hi, int n4) {
    for (int i = blockIdx.x * blockDim.x + threadIdx.x; i < n4;
         i += gridDim.x * blockDim.x) {
        float4 v = ((const float4*)src)[i];
        __half2 h0 = __floats2half2_rn(v.x, v.y);
        __half2 h1 = __floats2half2_rn(v.z, v.w);
        uint2 h;
        h.x = *(uint32_t*)&h0;
        h.y = *(uint32_t*)&h1;
        ((uint2*)hi)[i] = h;
    }
}

// ============================================================================
// fp16x2 GEMM (split-A only):  C = (Ah+Al) @ Bh^T + bias
// CTA tile 256x128, K-chunk 64, 2-stage cp.async, 8 warps (4m x 2n),
// warp tile 64x64. 2 product passes (Ah*Bh, Al*Bh).
// ============================================================================
#define GKC    64
#define GPITCH 72
#define GA_TILE (256 * GPITCH * 2)               // 36864
#define GB_TILE (128 * GPITCH * 2)               // 18432
#define GSTAGE_B (2 * GA_TILE + GB_TILE)         // 92160
#define G_SMEM_BYTES (2 * GSTAGE_B)              // 184320

__global__ __launch_bounds__(256, 1) void gemm_f16(
    int M, int N_, int K,
    const __half* __restrict__ Ah, const __half* __restrict__ Al,
    const __half* __restrict__ Bh,
    const float* __restrict__ bias,
    float* __restrict__ C,
    __half* __restrict__ Ch, __half* __restrict__ Cl)
{
    extern __shared__ __align__(16) char sm[];
    const uint32_t sb0 = smem_u32(sm);

    const int tid = threadIdx.x;
    const int wid = tid >> 5;
    const int lane = tid & 31;
    const int n0 = blockIdx.x * 128;
    const int m0 = blockIdx.y * 256;
    const int warp_m = wid & 3;
    const int warp_n = wid >> 2;

    float acc[4][8][4];
#pragma unroll
    for (int mt = 0; mt < 4; mt++)
#pragma unroll
        for (int nt = 0; nt < 8; nt++)
#pragma unroll
            for (int r = 0; r < 4; r++) acc[mt][nt][r] = 0.0f;

    const int a_row = warp_m * 64 + (lane & 7) + ((lane >> 3) & 1) * 8;
    const int a_kof = ((lane >> 4) & 1) * 8;
    const int b_row = warp_n * 64 + (lane & 7) + ((lane >> 4) & 1) * 8;
    const int b_kof = ((lane >> 3) & 1) * 8;

    const int nchunk = K / GKC;

    auto issue_chunk = [&](int ic, int s) {
        const uint32_t sb = sb0 + (uint32_t)s * GSTAGE_B;
        const int kc = ic * GKC;
#pragma unroll
        for (int i = 0; i < 8; i++) {
            const int id = tid + 256 * i;
            const int row = id >> 3;
            const int c8 = (id & 7) * 8;
            const uint32_t so = (uint32_t)(row * GPITCH + c8) * 2;
            const size_t ga = (size_t)(m0 + row) * K + kc + c8;
            cp16(sb + so,           Ah + ga);
            cp16(sb + GA_TILE + so, Al + ga);
        }
#pragma unroll
        for (int i = 0; i < 4; i++) {
            const int id = tid + 256 * i;
            const int row = id >> 3;
            const int c8 = (id & 7) * 8;
            const uint32_t so = (uint32_t)(row * GPITCH + c8) * 2;
            const size_t gb = (size_t)(n0 + row) * K + kc + c8;
            cp16(sb + 2 * GA_TILE + so, Bh + gb);
        }
    };

    issue_chunk(0, 0); CP_COMMIT();

    for (int ic = 0; ic < nchunk; ic++) {
        if (ic + 1 < nchunk) {
            issue_chunk(ic + 1, (ic + 1) & 1); CP_COMMIT();
            CP_WAIT(1);
        } else {
            CP_WAIT(0);
        }
        __syncthreads();

        const uint32_t sb  = sb0 + (uint32_t)(ic & 1) * GSTAGE_B;
        const uint32_t sAh = sb;
        const uint32_t sAl = sb + GA_TILE;
        const uint32_t sBh = sb + 2 * GA_TILE;

#pragma unroll
        for (int ks = 0; ks < 4; ks++) {
            const int k16 = ks * 16;
            uint32_t ah[4][4], al[4][4];
#pragma unroll
            for (int mt = 0; mt < 4; mt++) {
                const uint32_t aoff =
                    (uint32_t)((a_row + mt * 16) * GPITCH + k16 + a_kof) * 2;
                ldsm_x4(ah[mt][0], ah[mt][1], ah[mt][2], ah[mt][3], sAh + aoff);
                ldsm_x4(al[mt][0], al[mt][1], al[mt][2], al[mt][3], sAl + aoff);
            }
            uint32_t bh[8][2];
#pragma unroll
            for (int ntp = 0; ntp < 4; ntp++) {
                const uint32_t boff =
                    (uint32_t)((b_row + ntp * 16) * GPITCH + k16 + b_kof) * 2;
                ldsm_x4(bh[2 * ntp][0], bh[2 * ntp][1],
                        bh[2 * ntp + 1][0], bh[2 * ntp + 1][1], sBh + boff);
            }
#pragma unroll
            for (int mt = 0; mt < 4; mt++)
#pragma unroll
                for (int nt = 0; nt < 8; nt++)
                    mma_f16(acc[mt][nt], ah[mt], bh[nt]);
#pragma unroll
            for (int mt = 0; mt < 4; mt++)
#pragma unroll
                for (int nt = 0; nt < 8; nt++)
                    mma_f16(acc[mt][nt], al[mt], bh[nt]);
        }
        __syncthreads();
    }

    // Epilogue
    const int er0 = m0 + warp_m * 64 + (lane >> 2);
    const int ec0 = n0 + warp_n * 64 + (lane & 3) * 2;
#pragma unroll
    for (int mt = 0; mt < 4; mt++) {
#pragma unroll
        for (int nt = 0; nt < 8; nt++) {
            const int col = ec0 + nt * 8;
            const float bx = bias[col], by = bias[col + 1];
            const size_t o0 = (size_t)(er0 + mt * 16) * N_ + col;
            const size_t o1 = (size_t)(er0 + mt * 16 + 8) * N_ + col;
            const float c00 = acc[mt][nt][0] + bx, c01 = acc[mt][nt][1] + by;
            const float c10 = acc[mt][nt][2] + bx, c11 = acc[mt][nt][3] + by;
            if (C) {
                *(float2*)(C + o0) = make_float2(c00, c01);
                *(float2*)(C + o1) = make_float2(c10, c11);
            } else {
                uint32_t h0, l0w, h1, l1w;
                split2h(c00, c01, h0, l0w);
                split2h(c10, c11, h1, l1w);
                *(uint32_t*)(Ch + o0) = h0;  *(uint32_t*)(Cl + o0) = l0w;
                *(uint32_t*)(Ch + o1) = h1;  *(uint32_t*)(Cl + o1) = l1w;
            }
        }
    }
}

// ============================================================================
// Flash attention, tensor cores, fp16 split-A scheme.
// Q split hi/lo; K, V single fp16 (hi arrays). P split in registers.
// smem: Qh,Ql [128][72]; Kh,Vth [64][72]   (Vt = V transposed [dim][key])
// ============================================================================
#define APITCH 72
#define A_QTILE (128 * APITCH * 2)
#define A_KTILE (64 * APITCH * 2)
#define A_SMEM_BYTES (2 * A_QTILE + 2 * A_KTILE)   // 55296

__global__ __launch_bounds__(256, 1) void attn_tc(
    const __half* __restrict__ qkvh,
    const __half* __restrict__ qkvl,
    __half* __restrict__ aoh,
    __half* __restrict__ aol)
{
    extern __shared__ __align__(16) char smema[];
    const uint32_t sQh  = smem_u32(smema);
    const uint32_t sQl  = sQh + A_QTILE;
    const uint32_t sKh  = sQl + A_QTILE;
    const uint32_t sVth = sKh + A_KTILE;
    __half* pVth = (__half*)(smema + 2 * A_QTILE + A_KTILE);

    const int qt = gridDim.x - 1 - blockIdx.x;
    const int h  = blockIdx.y;
    const int b  = blockIdx.z;
    const int tid = threadIdx.x;
    const int wid = tid >> 5;
    const int lane = tid & 31;

    const size_t bN = (size_t)b * SEQ;
    const int qcol = h * HD;
    const int kcol = DIM + h * HD;
    const int vcol = 2 * DIM + h * HD;

#pragma unroll
    for (int i = 0; i < 4; i++) {
        const int id = tid + 256 * i;
        const int row = id >> 3;
        const int c8 = (id & 7) * 8;
        const uint32_t so = (uint32_t)(row * APITCH + c8) * 2;
        const size_t g = (bN + qt * 128 + row) * QKVD + qcol + c8;
        cp16(sQh + so, qkvh + g);
        cp16(sQl + so, qkvl + g);
    }
    CP_COMMIT();
    CP_WAIT(0);
    __syncthreads();

    const int a_row = wid * 16 + (lane & 7) + ((lane >> 3) & 1) * 8;
    const int a_kof = ((lane >> 4) & 1) * 8;
    uint32_t qh[4][4], ql[4][4];
#pragma unroll
    for (int ks = 0; ks < 4; ks++) {
        const uint32_t off = (uint32_t)(a_row * APITCH + ks * 16 + a_kof) * 2;
        ldsm_x4(qh[ks][0], qh[ks][1], qh[ks][2], qh[ks][3], sQh + off);
        ldsm_x4(ql[ks][0], ql[ks][1], ql[ks][2], ql[ks][3], sQl + off);
    }
    __syncthreads();

    const int b_row = (lane & 7) + ((lane >> 4) & 1) * 8;
    const int b_kof = ((lane >> 3) & 1) * 8;

    float o[8][4];
#pragma unroll
    for (int nt = 0; nt < 8; nt++)
#pragma unroll
        for (int r = 0; r < 4; r++) o[nt][r] = 0.0f;
    float m0 = -1e30f, m1 = -1e30f, l0 = 0.0f, l1 = 0.0f;

    const float scale = 0.125f;
    const int row_lo = qt * 128 + wid * 16 + (lane >> 2);
    const int row_hi = row_lo + 8;
    const int ntiles = (qt + 1) * 2;

    const int vrr = tid >> 2;
    const int vd0 = (tid & 3) * 16;

    for (int kt = 0; kt < ntiles; kt++) {
        const int kb = kt * 64;

#pragma unroll
        for (int i = 0; i < 2; i++) {
            const int id = tid + 256 * i;
            const int row = id >> 3;
            const int c8 = (id & 7) * 8;
            const uint32_t so = (uint32_t)(row * APITCH + c8) * 2;
            const size_t g = (bN + kb + row) * QKVD + kcol + c8;
            cp16(sKh + so, qkvh + g);
        }
        {
            const size_t g = (bN + kb + vrr) * QKVD + vcol + vd0;
            union { uint4 q; __half e[8]; } uh0, uh1;
            uh0.q = *(const uint4*)(qkvh + g);
            uh1.q = *(const uint4*)(qkvh + g + 8);
#pragma unroll
            for (int e = 0; e < 8; e++) {
                pVth[(vd0 + e) * APITCH + vrr]     = uh0.e[e];
                pVth[(vd0 + 8 + e) * APITCH + vrr] = uh1.e[e];
            }
        }
        CP_COMMIT();
        CP_WAIT(0);
        __syncthreads();

        float s[8][4];
#pragma unroll
        for (int nt = 0; nt < 8; nt++)
#pragma unroll
            for (int r = 0; r < 4; r++) s[nt][r] = 0.0f;

#pragma unroll
        for (int ks = 0; ks < 4; ks++) {
            uint32_t kh[8][2];
#pragma unroll
            for (int ntp = 0; ntp < 4; ntp++) {
                const uint32_t off =
                    (uint32_t)((ntp * 16 + b_row) * APITCH + ks * 16 + b_kof) * 2;
                ldsm_x4(kh[2 * ntp][0], kh[2 * ntp][1],
                        kh[2 * ntp + 1][0], kh[2 * ntp + 1][1], sKh + off);
            }
#pragma unroll
            for (int nt = 0; nt < 8; nt++) mma_f16(s[nt], qh[ks], kh[nt]);
#pragma unroll
            for (int nt = 0; nt < 8; nt++) mma_f16(s[nt], ql[ks], kh[nt]);
        }

        const bool full = (kb + 63) <= qt * 128;
        if (full) {
#pragma unroll
            for (int nt = 0; nt < 8; nt++)
#pragma unroll
                for (int r = 0; r < 4; r++) s[nt][r] *= scale;
        } else {
#pragma unroll
            for (int nt = 0; nt < 8; nt++) {
                const int col = kb + nt * 8 + (lane & 3) * 2;
                s[nt][0] = (col     <= row_lo) ? s[nt][0] * scale : -1e30f;
                s[nt][1] = (col + 1 <= row_lo) ? s[nt][1] * scale : -1e30f;
                s[nt][2] = (col     <= row_hi) ? s[nt][2] * scale : -1e30f;
                s[nt][3] = (col + 1 <= row_hi) ? s[nt][3] * scale : -1e30f;
            }
        }

        float tm0 = -1e30f, tm1 = -1e30f;
#pragma unroll
        for (int nt = 0; nt < 8; nt++) {
            tm0 = fmaxf(tm0, fmaxf(s[nt][0], s[nt][1]));
            tm1 = fmaxf(tm1, fmaxf(s[nt][2], s[nt][3]));
        }
        tm0 = fmaxf(tm0, __shfl_xor_sync(0xffffffffu, tm0, 1));
        tm0 = fmaxf(tm0, __shfl_xor_sync(0xffffffffu, tm0, 2));
        tm1 = fmaxf(tm1, __shfl_xor_sync(0xffffffffu, tm1, 1));
        tm1 = fmaxf(tm1, __shfl_xor_sync(0xffffffffu, tm1, 2));

        const float nm0 = fmaxf(m0, tm0);
        const float nm1 = fmaxf(m1, tm1);
        const float corr0 = __expf(m0 - nm0);
        const float corr1 = __expf(m1 - nm1);

        float ps0 = 0.0f, ps1 = 0.0f;
#pragma unroll
        for (int nt = 0; nt < 8; nt++) {
            s[nt][0] = __expf(s[nt][0] - nm0); ps0 += s[nt][0];
            s[nt][1] = __expf(s[nt][1] - nm0); ps0 += s[nt][1];
            s[nt][2] = __expf(s[nt][2] - nm1); ps1 += s[nt][2];
            s[nt][3] = __expf(s[nt][3] - nm1); ps1 += s[nt][3];
        }
        ps0 += __shfl_xor_sync(0xffffffffu, ps0, 1);
        ps0 += __shfl_xor_sync(0xffffffffu, ps0, 2);
        ps1 += __shfl_xor_sync(0xffffffffu, ps1, 1);
        ps1 += __shfl_xor_sync(0xffffffffu, ps1, 2);

        l0 = l0 * corr0 + ps0; m0 = nm0;
        l1 = l1 * corr1 + ps1; m1 = nm1;
#pragma unroll
        for (int nt = 0; nt < 8; nt++) {
            o[nt][0] *= corr0; o[nt][1] *= corr0;
            o[nt][2] *= corr1; o[nt][3] *= corr1;
        }

        // P repack (fp16 split) + V fragments, then 2 product passes.
        uint32_t pah[4][4], pal[4][4], vh[4][8][2];
#pragma unroll
        for (int ks = 0; ks < 4; ks++) {
            const int j = 2 * ks;
            split2h(s[j][0],     s[j][1],     pah[ks][0], pal[ks][0]);
            split2h(s[j][2],     s[j][3],     pah[ks][1], pal[ks][1]);
            split2h(s[j + 1][0], s[j + 1][1], pah[ks][2], pal[ks][2]);
            split2h(s[j + 1][2], s[j + 1][3], pah[ks][3], pal[ks][3]);
#pragma unroll
            for (int ntp = 0; ntp < 4; ntp++) {
                const uint32_t off =
                    (uint32_t)((ntp * 16 + b_row) * APITCH + ks * 16 + b_kof) * 2;
                ldsm_x4(vh[ks][2 * ntp][0], vh[ks][2 * ntp][1],
                        vh[ks][2 * ntp + 1][0], vh[ks][2 * ntp + 1][1], sVth + off);
            }
        }
#pragma unroll
        for (int ks = 0; ks < 4; ks++)
#pragma unroll
            for (int nt = 0; nt < 8; nt++) mma_f16(o[nt], pah[ks], vh[ks][nt]);
#pragma unroll
        for (int ks = 0; ks < 4; ks++)
#pragma unroll
            for (int nt = 0; nt < 8; nt++) mma_f16(o[nt], pal[ks], vh[ks][nt]);
        __syncthreads();
    }

    const float inv0 = 1.0f / l0;
    const float inv1 = 1.0f / l1;
#pragma unroll
    for (int nt = 0; nt < 8; nt++) {
        const int col = h * HD + nt * 8 + (lane & 3) * 2;
        const size_t o0 = (bN + row_lo) * DIM + col;
        const size_t o1 = (bN + row_hi) * DIM + col;
        uint32_t h0, l0w, h1, l1w;
        split2h(o[nt][0] * inv0, o[nt][1] * inv0, h0, l0w);
        split2h(o[nt][2] * inv1, o[nt][3] * inv1, h1, l1w);
        *(uint32_t*)(aoh + o0) = h0;  *(uint32_t*)(aol + o0) = l0w;
        *(uint32_t*)(aoh + o1) = h1;  *(uint32_t*)(aol + o1) = l1w;
    }
}

// ---------------------------------------------------------------------------
extern "C" void kernel_launch(void* const* d_in, const int* in_sizes, int n_in,
                              void* d_out, int out_size)
{
    const float* x     = (const float*)d_in[0];
    const float* W_qkv = (const float*)d_in[1];
    const float* b_qkv = (const float*)d_in[2];
    const float* W_out = (const float*)d_in[3];
    const float* b_out = (const float*)d_in[4];
    float* out = (float*)d_out;

    __half *xh, *xl, *wqh, *woh, *qkvh, *qkvl, *aoh, *aol;
    cudaGetSymbolAddress((void**)&xh,  g_xh);   cudaGetSymbolAddress((void**)&xl,  g_xl);
    cudaGetSymbolAddress((void**)&wqh, g_wqh);  cudaGetSymbolAddress((void**)&woh, g_woh);
    cudaGetSymbolAddress((void**)&qkvh, g_qkvh); cudaGetSymbolAddress((void**)&qkvl, g_qkvl);
    cudaGetSymbolAddress((void**)&aoh, g_aoh);  cudaGetSymbolAddress((void**)&aol, g_aol);

    cudaFuncSetAttribute(gemm_f16,
                         cudaFuncAttributeMaxDynamicSharedMemorySize, G_SMEM_BYTES);
    cudaFuncSetAttribute(attn_tc,
                         cudaFuncAttributeMaxDynamicSharedMemorySize, A_SMEM_BYTES);

    const int M = BATCH * SEQ;  // 4096

    // 0) Pre-split A-side (x); round B-side weights to fp16
    split_arr<<<1024, 256>>>(x,     xh,  xl, M * DIM / 4);
    round_arr<<<1024, 256>>>(W_qkv, wqh,     QKVD * DIM / 4);
    round_arr<<<512,  256>>>(W_out, woh,     DIM * DIM / 4);

    // 1) QKV projection -> split fp16 qkv
    {
        dim3 grid(QKVD / 128, M / 256);
        gemm_f16<<<grid, 256, G_SMEM_BYTES>>>(M, QKVD, DIM, xh, xl, wqh,
                                              b_qkv, nullptr, qkvh, qkvl);
    }
    // 2) Attention -> split fp16 aout
    {
        dim3 grid(SEQ / 128, HEADS, BATCH);
        attn_tc<<<grid, 256, A_SMEM_BYTES>>>(qkvh, qkvl, aoh, aol);
    }
    // 3) Output projection -> fp32 out
    {
        dim3 grid(DIM / 128, M / 256);
        gemm_f16<<<grid, 256, G_SMEM_BYTES>>>(M, DIM, DIM, aoh, aol, woh,
                                              b_out, out, nullptr, nullptr);
    }
}

// round 11
// speedup vs baseline: 1.4369x; 1.0354x over previous
#include <cuda_runtime.h>
#include <cuda_fp16.h>
#include <math.h>
#include <stdint.h>

// Problem constants
#define BATCH 2
#define SEQ   2048
#define DIM   1024
#define HEADS 16
#define HD    64
#define QKVD  3072   // 3*DIM

// ---------------------------------------------------------------------------
// Global scratch (alloc-free rule). hi/lo fp16 pairs represent fp32 (A-side);
// B-side operands are single fp16 (one rounding, 2^-12 rel).
// ---------------------------------------------------------------------------
__device__ __half g_xh [(size_t)BATCH * SEQ * DIM];
__device__ __half g_xl [(size_t)BATCH * SEQ * DIM];
__device__ __half g_wqh[(size_t)QKVD * DIM];
__device__ __half g_woh[(size_t)DIM * DIM];
__device__ __half g_qkvh[(size_t)BATCH * SEQ * QKVD];
__device__ __half g_qkvl[(size_t)BATCH * SEQ * QKVD];
__device__ __half g_aoh[(size_t)BATCH * SEQ * DIM];
__device__ __half g_aol[(size_t)BATCH * SEQ * DIM];

// ============================================================================
// Helpers (generic PTX, compute_103-safe)
// ============================================================================
__device__ __forceinline__ uint32_t smem_u32(const void* p) {
    uint32_t a;
    asm("{ .reg .u64 t; cvta.to.shared.u64 t, %1; cvt.u32.u64 %0, t; }"
        : "=r"(a) : "l"(p));
    return a;
}
__device__ __forceinline__ void ldsm_x4(uint32_t& r0, uint32_t& r1,
                                        uint32_t& r2, uint32_t& r3,
                                        uint32_t addr) {
    asm volatile("ldmatrix.sync.aligned.m8n8.x4.shared.b16 {%0,%1,%2,%3}, [%4];"
                 : "=r"(r0), "=r"(r1), "=r"(r2), "=r"(r3) : "r"(addr));
}
__device__ __forceinline__ void mma_f16(float* d, const uint32_t* a,
                                        const uint32_t* b) {
    asm volatile(
        "mma.sync.aligned.m16n8k16.row.col.f32.f16.f16.f32 "
        "{%0,%1,%2,%3}, {%4,%5,%6,%7}, {%8,%9}, {%0,%1,%2,%3};"
        : "+f"(d[0]), "+f"(d[1]), "+f"(d[2]), "+f"(d[3])
        : "r"(a[0]), "r"(a[1]), "r"(a[2]), "r"(a[3]), "r"(b[0]), "r"(b[1]));
}
// fp32 pair -> fp16 hi + fp16 lo (residual), packed as half2 words
__device__ __forceinline__ void split2h(float x, float y,
                                        uint32_t& hi, uint32_t& lo) {
    __half2 h = __floats2half2_rn(x, y);
    float rx = x - __half2float(__low2half(h));
    float ry = y - __half2float(__high2half(h));
    __half2 l = __floats2half2_rn(rx, ry);
    hi = *(uint32_t*)&h;
    lo = *(uint32_t*)&l;
}
__device__ __forceinline__ void cp16(uint32_t smem, const void* gmem) {
    asm volatile("cp.async.cg.shared.global [%0], [%1], 16;"
                 :: "r"(smem), "l"(gmem));
}
#define CP_COMMIT() asm volatile("cp.async.commit_group;" ::: "memory")
#define CP_WAIT(n)  asm volatile("cp.async.wait_group %0;" :: "n"(n) : "memory")

// ============================================================================
// split_arr: fp32 -> (fp16 hi, fp16 lo).   round_arr: fp32 -> fp16.
// ============================================================================
__global__ void split_arr(const float* __restrict__ src,
                          __half* __restrict__ hi,
                          __half* __restrict__ lo, int n4) {
    for (int i = blockIdx.x * blockDim.x + threadIdx.x; i < n4;
         i += gridDim.x * blockDim.x) {
        float4 v = ((const float4*)src)[i];
        uint2 h, l;
        split2h(v.x, v.y, h.x, l.x);
        split2h(v.z, v.w, h.y, l.y);
        ((uint2*)hi)[i] = h;
        ((uint2*)lo)[i] = l;
    }
}
__global__ void round_arr(const float* __restrict__ src,
                          __half* __restrict__ hi, int n4) {
    for (int i = blockIdx.x * blockDim.x + threadIdx.x; i < n4;
         i += gridDim.x * blockDim.x) {
        float4 v = ((const float4*)src)[i];
        __half2 h0 = __floats2half2_rn(v.x, v.y);
        __half2 h1 = __floats2half2_rn(v.z, v.w);
        uint2 h;
        h.x = *(uint32_t*)&h0;
        h.y = *(uint32_t*)&h1;
        ((uint2*)hi)[i] = h;
    }
}

// ============================================================================
// fp16x2 GEMM (split-A only):  C = (Ah+Al) @ Bh^T + bias
// CTA tile 128x128, K-chunk 64, 2-stage cp.async, 8 warps (4m x 2n),
// warp tile 32x64. __launch_bounds__(256, 2) -> 2 CTAs/SM, 4 warps/SMSP
// for tensor-pipe latency hiding.
// ============================================================================
#define GKC    64
#define GPITCH 72
#define GA_TILE (128 * GPITCH * 2)               // 18432 (one of Ah/Al)
#define GB_TILE (128 * GPITCH * 2)               // 18432
#define GSTAGE_B (2 * GA_TILE + GB_TILE)         // 55296
#define G_SMEM_BYTES (2 * GSTAGE_B)              // 110592

__global__ __launch_bounds__(256, 2) void gemm_f16(
    int M, int N_, int K,
    const __half* __restrict__ Ah, const __half* __restrict__ Al,
    const __half* __restrict__ Bh,
    const float* __restrict__ bias,
    float* __restrict__ C,
    __half* __restrict__ Ch, __half* __restrict__ Cl)
{
    extern __shared__ __align__(16) char sm[];
    const uint32_t sb0 = smem_u32(sm);

    const int tid = threadIdx.x;
    const int wid = tid >> 5;
    const int lane = tid & 31;
    const int n0 = blockIdx.x * 128;
    const int m0 = blockIdx.y * 128;
    const int warp_m = wid & 3;         // 32-row slice
    const int warp_n = wid >> 2;        // 64-col slice

    float acc[2][8][4];
#pragma unroll
    for (int mt = 0; mt < 2; mt++)
#pragma unroll
        for (int nt = 0; nt < 8; nt++)
#pragma unroll
            for (int r = 0; r < 4; r++) acc[mt][nt][r] = 0.0f;

    const int a_row = warp_m * 32 + (lane & 7) + ((lane >> 3) & 1) * 8;
    const int a_kof = ((lane >> 4) & 1) * 8;
    const int b_row = warp_n * 64 + (lane & 7) + ((lane >> 4) & 1) * 8;
    const int b_kof = ((lane >> 3) & 1) * 8;

    const int nchunk = K / GKC;

    auto issue_chunk = [&](int ic, int s) {
        const uint32_t sb = sb0 + (uint32_t)s * GSTAGE_B;
        const int kc = ic * GKC;
#pragma unroll
        for (int i = 0; i < 4; i++) {
            const int id = tid + 256 * i;      // 0..1023
            const int row = id >> 3;
            const int c8 = (id & 7) * 8;
            const uint32_t so = (uint32_t)(row * GPITCH + c8) * 2;
            const size_t ga = (size_t)(m0 + row) * K + kc + c8;
            const size_t gb = (size_t)(n0 + row) * K + kc + c8;
            cp16(sb + so,               Ah + ga);
            cp16(sb + GA_TILE + so,     Al + ga);
            cp16(sb + 2 * GA_TILE + so, Bh + gb);
        }
    };

    issue_chunk(0, 0); CP_COMMIT();

    for (int ic = 0; ic < nchunk; ic++) {
        if (ic + 1 < nchunk) {
            issue_chunk(ic + 1, (ic + 1) & 1); CP_COMMIT();
            CP_WAIT(1);
        } else {
            CP_WAIT(0);
        }
        __syncthreads();

        const uint32_t sb  = sb0 + (uint32_t)(ic & 1) * GSTAGE_B;
        const uint32_t sAh = sb;
        const uint32_t sAl = sb + GA_TILE;
        const uint32_t sBh = sb + 2 * GA_TILE;

#pragma unroll
        for (int ks = 0; ks < 4; ks++) {
            const int k16 = ks * 16;
            uint32_t ah[2][4], al[2][4];
#pragma unroll
            for (int mt = 0; mt < 2; mt++) {
                const uint32_t aoff =
                    (uint32_t)((a_row + mt * 16) * GPITCH + k16 + a_kof) * 2;
                ldsm_x4(ah[mt][0], ah[mt][1], ah[mt][2], ah[mt][3], sAh + aoff);
                ldsm_x4(al[mt][0], al[mt][1], al[mt][2], al[mt][3], sAl + aoff);
            }
            uint32_t bh[8][2];
#pragma unroll
            for (int ntp = 0; ntp < 4; ntp++) {
                const uint32_t boff =
                    (uint32_t)((b_row + ntp * 16) * GPITCH + k16 + b_kof) * 2;
                ldsm_x4(bh[2 * ntp][0], bh[2 * ntp][1],
                        bh[2 * ntp + 1][0], bh[2 * ntp + 1][1], sBh + boff);
            }
#pragma unroll
            for (int mt = 0; mt < 2; mt++)
#pragma unroll
                for (int nt = 0; nt < 8; nt++)
                    mma_f16(acc[mt][nt], ah[mt], bh[nt]);
#pragma unroll
            for (int mt = 0; mt < 2; mt++)
#pragma unroll
                for (int nt = 0; nt < 8; nt++)
                    mma_f16(acc[mt][nt], al[mt], bh[nt]);
        }
        __syncthreads();
    }

    // Epilogue
    const int er0 = m0 + warp_m * 32 + (lane >> 2);
    const int ec0 = n0 + warp_n * 64 + (lane & 3) * 2;
#pragma unroll
    for (int mt = 0; mt < 2; mt++) {
#pragma unroll
        for (int nt = 0; nt < 8; nt++) {
            const int col = ec0 + nt * 8;
            const float bx = bias[col], by = bias[col + 1];
            const size_t o0 = (size_t)(er0 + mt * 16) * N_ + col;
            const size_t o1 = (size_t)(er0 + mt * 16 + 8) * N_ + col;
            const float c00 = acc[mt][nt][0] + bx, c01 = acc[mt][nt][1] + by;
            const float c10 = acc[mt][nt][2] + bx, c11 = acc[mt][nt][3] + by;
            if (C) {
                *(float2*)(C + o0) = make_float2(c00, c01);
                *(float2*)(C + o1) = make_float2(c10, c11);
            } else {
                uint32_t h0, l0w, h1, l1w;
                split2h(c00, c01, h0, l0w);
                split2h(c10, c11, h1, l1w);
                *(uint32_t*)(Ch + o0) = h0;  *(uint32_t*)(Cl + o0) = l0w;
                *(uint32_t*)(Ch + o1) = h1;  *(uint32_t*)(Cl + o1) = l1w;
            }
        }
    }
}

// ============================================================================
// Flash attention, tensor cores, fp16 split-A scheme (unchanged R10).
// ============================================================================
#define APITCH 72
#define A_QTILE (128 * APITCH * 2)
#define A_KTILE (64 * APITCH * 2)
#define A_SMEM_BYTES (2 * A_QTILE + 2 * A_KTILE)   // 55296

__global__ __launch_bounds__(256, 1) void attn_tc(
    const __half* __restrict__ qkvh,
    const __half* __restrict__ qkvl,
    __half* __restrict__ aoh,
    __half* __restrict__ aol)
{
    extern __shared__ __align__(16) char smema[];
    const uint32_t sQh  = smem_u32(smema);
    const uint32_t sQl  = sQh + A_QTILE;
    const uint32_t sKh  = sQl + A_QTILE;
    const uint32_t sVth = sKh + A_KTILE;
    __half* pVth = (__half*)(smema + 2 * A_QTILE + A_KTILE);

    const int qt = gridDim.x - 1 - blockIdx.x;
    const int h  = blockIdx.y;
    const int b  = blockIdx.z;
    const int tid = threadIdx.x;
    const int wid = tid >> 5;
    const int lane = tid & 31;

    const size_t bN = (size_t)b * SEQ;
    const int qcol = h * HD;
    const int kcol = DIM + h * HD;
    const int vcol = 2 * DIM + h * HD;

#pragma unroll
    for (int i = 0; i < 4; i++) {
        const int id = tid + 256 * i;
        const int row = id >> 3;
        const int c8 = (id & 7) * 8;
        const uint32_t so = (uint32_t)(row * APITCH + c8) * 2;
        const size_t g = (bN + qt * 128 + row) * QKVD + qcol + c8;
        cp16(sQh + so, qkvh + g);
        cp16(sQl + so, qkvl + g);
    }
    CP_COMMIT();
    CP_WAIT(0);
    __syncthreads();

    const int a_row = wid * 16 + (lane & 7) + ((lane >> 3) & 1) * 8;
    const int a_kof = ((lane >> 4) & 1) * 8;
    uint32_t qh[4][4], ql[4][4];
#pragma unroll
    for (int ks = 0; ks < 4; ks++) {
        const uint32_t off = (uint32_t)(a_row * APITCH + ks * 16 + a_kof) * 2;
        ldsm_x4(qh[ks][0], qh[ks][1], qh[ks][2], qh[ks][3], sQh + off);
        ldsm_x4(ql[ks][0], ql[ks][1], ql[ks][2], ql[ks][3], sQl + off);
    }
    __syncthreads();

    const int b_row = (lane & 7) + ((lane >> 4) & 1) * 8;
    const int b_kof = ((lane >> 3) & 1) * 8;

    float o[8][4];
#pragma unroll
    for (int nt = 0; nt < 8; nt++)
#pragma unroll
        for (int r = 0; r < 4; r++) o[nt][r] = 0.0f;
    float m0 = -1e30f, m1 = -1e30f, l0 = 0.0f, l1 = 0.0f;

    const float scale = 0.125f;
    const int row_lo = qt * 128 + wid * 16 + (lane >> 2);
    const int row_hi = row_lo + 8;
    const int ntiles = (qt + 1) * 2;

    const int vrr = tid >> 2;
    const int vd0 = (tid & 3) * 16;

    for (int kt = 0; kt < ntiles; kt++) {
        const int kb = kt * 64;

#pragma unroll
        for (int i = 0; i < 2; i++) {
            const int id = tid + 256 * i;
            const int row = id >> 3;
            const int c8 = (id & 7) * 8;
            const uint32_t so = (uint32_t)(row * APITCH + c8) * 2;
            const size_t g = (bN + kb + row) * QKVD + kcol + c8;
            cp16(sKh + so, qkvh + g);
        }
        {
            const size_t g = (bN + kb + vrr) * QKVD + vcol + vd0;
            union { uint4 q; __half e[8]; } uh0, uh1;
            uh0.q = *(const uint4*)(qkvh + g);
            uh1.q = *(const uint4*)(qkvh + g + 8);
#pragma unroll
            for (int e = 0; e < 8; e++) {
                pVth[(vd0 + e) * APITCH + vrr]     = uh0.e[e];
                pVth[(vd0 + 8 + e) * APITCH + vrr] = uh1.e[e];
            }
        }
        CP_COMMIT();
        CP_WAIT(0);
        __syncthreads();

        float s[8][4];
#pragma unroll
        for (int nt = 0; nt < 8; nt++)
#pragma unroll
            for (int r = 0; r < 4; r++) s[nt][r] = 0.0f;

#pragma unroll
        for (int ks = 0; ks < 4; ks++) {
            uint32_t kh[8][2];
#pragma unroll
            for (int ntp = 0; ntp < 4; ntp++) {
                const uint32_t off =
                    (uint32_t)((ntp * 16 + b_row) * APITCH + ks * 16 + b_kof) * 2;
                ldsm_x4(kh[2 * ntp][0], kh[2 * ntp][1],
                        kh[2 * ntp + 1][0], kh[2 * ntp + 1][1], sKh + off);
            }
#pragma unroll
            for (int nt = 0; nt < 8; nt++) mma_f16(s[nt], qh[ks], kh[nt]);
#pragma unroll
            for (int nt = 0; nt < 8; nt++) mma_f16(s[nt], ql[ks], kh[nt]);
        }

        const bool full = (kb + 63) <= qt * 128;
        if (full) {
#pragma unroll
            for (int nt = 0; nt < 8; nt++)
#pragma unroll
                for (int r = 0; r < 4; r++) s[nt][r] *= scale;
        } else {
#pragma unroll
            for (int nt = 0; nt < 8; nt++) {
                const int col = kb + nt * 8 + (lane & 3) * 2;
                s[nt][0] = (col     <= row_lo) ? s[nt][0] * scale : -1e30f;
                s[nt][1] = (col + 1 <= row_lo) ? s[nt][1] * scale : -1e30f;
                s[nt][2] = (col     <= row_hi) ? s[nt][2] * scale : -1e30f;
                s[nt][3] = (col + 1 <= row_hi) ? s[nt][3] * scale : -1e30f;
            }
        }

        float tm0 = -1e30f, tm1 = -1e30f;
#pragma unroll
        for (int nt = 0; nt < 8; nt++) {
            tm0 = fmaxf(tm0, fmaxf(s[nt][0], s[nt][1]));
            tm1 = fmaxf(tm1, fmaxf(s[nt][2], s[nt][3]));
        }
        tm0 = fmaxf(tm0, __shfl_xor_sync(0xffffffffu, tm0, 1));
        tm0 = fmaxf(tm0, __shfl_xor_sync(0xffffffffu, tm0, 2));
        tm1 = fmaxf(tm1, __shfl_xor_sync(0xffffffffu, tm1, 1));
        tm1 = fmaxf(tm1, __shfl_xor_sync(0xffffffffu, tm1, 2));

        const float nm0 = fmaxf(m0, tm0);
        const float nm1 = fmaxf(m1, tm1);
        const float corr0 = __expf(m0 - nm0);
        const float corr1 = __expf(m1 - nm1);

        float ps0 = 0.0f, ps1 = 0.0f;
#pragma unroll
        for (int nt = 0; nt < 8; nt++) {
            s[nt][0] = __expf(s[nt][0] - nm0); ps0 += s[nt][0];
            s[nt][1] = __expf(s[nt][1] - nm0); ps0 += s[nt][1];
            s[nt][2] = __expf(s[nt][2] - nm1); ps1 += s[nt][2];
            s[nt][3] = __expf(s[nt][3] - nm1); ps1 += s[nt][3];
        }
        ps0 += __shfl_xor_sync(0xffffffffu, ps0, 1);
        ps0 += __shfl_xor_sync(0xffffffffu, ps0, 2);
        ps1 += __shfl_xor_sync(0xffffffffu, ps1, 1);
        ps1 += __shfl_xor_sync(0xffffffffu, ps1, 2);

        l0 = l0 * corr0 + ps0; m0 = nm0;
        l1 = l1 * corr1 + ps1; m1 = nm1;
#pragma unroll
        for (int nt = 0; nt < 8; nt++) {
            o[nt][0] *= corr0; o[nt][1] *= corr0;
            o[nt][2] *= corr1; o[nt][3] *= corr1;
        }

        // P repack (fp16 split) + V fragments, then 2 product passes.
        uint32_t pah[4][4], pal[4][4], vh[4][8][2];
#pragma unroll
        for (int ks = 0; ks < 4; ks++) {
            const int j = 2 * ks;
            split2h(s[j][0],     s[j][1],     pah[ks][0], pal[ks][0]);
            split2h(s[j][2],     s[j][3],     pah[ks][1], pal[ks][1]);
            split2h(s[j + 1][0], s[j + 1][1], pah[ks][2], pal[ks][2]);
            split2h(s[j + 1][2], s[j + 1][3], pah[ks][3], pal[ks][3]);
#pragma unroll
            for (int ntp = 0; ntp < 4; ntp++) {
                const uint32_t off =
                    (uint32_t)((ntp * 16 + b_row) * APITCH + ks * 16 + b_kof) * 2;
                ldsm_x4(vh[ks][2 * ntp][0], vh[ks][2 * ntp][1],
                        vh[ks][2 * ntp + 1][0], vh[ks][2 * ntp + 1][1], sVth + off);
            }
        }
#pragma unroll
        for (int ks = 0; ks < 4; ks++)
#pragma unroll
            for (int nt = 0; nt < 8; nt++) mma_f16(o[nt], pah[ks], vh[ks][nt]);
#pragma unroll
        for (int ks = 0; ks < 4; ks++)
#pragma unroll
            for (int nt = 0; nt < 8; nt++) mma_f16(o[nt], pal[ks], vh[ks][nt]);
        __syncthreads();
    }

    const float inv0 = 1.0f / l0;
    const float inv1 = 1.0f / l1;
#pragma unroll
    for (int nt = 0; nt < 8; nt++) {
        const int col = h * HD + nt * 8 + (lane & 3) * 2;
        const size_t o0 = (bN + row_lo) * DIM + col;
        const size_t o1 = (bN + row_hi) * DIM + col;
        uint32_t h0, l0w, h1, l1w;
        split2h(o[nt][0] * inv0, o[nt][1] * inv0, h0, l0w);
        split2h(o[nt][2] * inv1, o[nt][3] * inv1, h1, l1w);
        *(uint32_t*)(aoh + o0) = h0;  *(uint32_t*)(aol + o0) = l0w;
        *(uint32_t*)(aoh + o1) = h1;  *(uint32_t*)(aol + o1) = l1w;
    }
}

// ---------------------------------------------------------------------------
extern "C" void kernel_launch(void* const* d_in, const int* in_sizes, int n_in,
                              void* d_out, int out_size)
{
    const float* x     = (const float*)d_in[0];
    const float* W_qkv = (const float*)d_in[1];
    const float* b_qkv = (const float*)d_in[2];
    const float* W_out = (const float*)d_in[3];
    const float* b_out = (const float*)d_in[4];
    float* out = (float*)d_out;

    __half *xh, *xl, *wqh, *woh, *qkvh, *qkvl, *aoh, *aol;
    cudaGetSymbolAddress((void**)&xh,  g_xh);   cudaGetSymbolAddress((void**)&xl,  g_xl);
    cudaGetSymbolAddress((void**)&wqh, g_wqh);  cudaGetSymbolAddress((void**)&woh, g_woh);
    cudaGetSymbolAddress((void**)&qkvh, g_qkvh); cudaGetSymbolAddress((void**)&qkvl, g_qkvl);
    cudaGetSymbolAddress((void**)&aoh, g_aoh);  cudaGetSymbolAddress((void**)&aol, g_aol);

    cudaFuncSetAttribute(gemm_f16,
                         cudaFuncAttributeMaxDynamicSharedMemorySize, G_SMEM_BYTES);
    cudaFuncSetAttribute(attn_tc,
                         cudaFuncAttributeMaxDynamicSharedMemorySize, A_SMEM_BYTES);

    const int M = BATCH * SEQ;  // 4096

    // 0) Pre-split A-side (x); round B-side weights to fp16
    split_arr<<<1024, 256>>>(x,     xh,  xl, M * DIM / 4);
    round_arr<<<1024, 256>>>(W_qkv, wqh,     QKVD * DIM / 4);
    round_arr<<<512,  256>>>(W_out, woh,     DIM * DIM / 4);

    // 1) QKV projection -> split fp16 qkv
    {
        dim3 grid(QKVD / 128, M / 128);
        gemm_f16<<<grid, 256, G_SMEM_BYTES>>>(M, QKVD, DIM, xh, xl, wqh,
                                              b_qkv, nullptr, qkvh, qkvl);
    }
    // 2) Attention -> split fp16 aout
    {
        dim3 grid(SEQ / 128, HEADS, BATCH);
        attn_tc<<<grid, 256, A_SMEM_BYTES>>>(qkvh, qkvl, aoh, aol);
    }
    // 3) Output projection -> fp32 out
    {
        dim3 grid(DIM / 128, M / 128);
        gemm_f16<<<grid, 256, G_SMEM_BYTES>>>(M, DIM, DIM, aoh, aol, woh,
                                              b_out, out, nullptr, nullptr);
    }
}

// round 12
// speedup vs baseline: 1.5402x; 1.0719x over previous
#include <cuda_runtime.h>
#include <cuda_fp16.h>
#include <math.h>
#include <stdint.h>

// Problem constants
#define BATCH 2
#define SEQ   2048
#define DIM   1024
#define HEADS 16
#define HD    64
#define QKVD  3072   // 3*DIM

// ---------------------------------------------------------------------------
// Global scratch (alloc-free rule). hi/lo fp16 pairs represent fp32 (A-side);
// B-side operands are single fp16 (one rounding, 2^-12 rel).
// ---------------------------------------------------------------------------
__device__ __half g_xh [(size_t)BATCH * SEQ * DIM];
__device__ __half g_xl [(size_t)BATCH * SEQ * DIM];
__device__ __half g_wqh[(size_t)QKVD * DIM];
__device__ __half g_woh[(size_t)DIM * DIM];
__device__ __half g_qkvh[(size_t)BATCH * SEQ * QKVD];
__device__ __half g_qkvl[(size_t)BATCH * SEQ * QKVD];
__device__ __half g_aoh[(size_t)BATCH * SEQ * DIM];
__device__ __half g_aol[(size_t)BATCH * SEQ * DIM];

// ============================================================================
// Helpers (generic PTX, compute_103-safe)
// ============================================================================
__device__ __forceinline__ uint32_t smem_u32(const void* p) {
    uint32_t a;
    asm("{ .reg .u64 t; cvta.to.shared.u64 t, %1; cvt.u32.u64 %0, t; }"
        : "=r"(a) : "l"(p));
    return a;
}
__device__ __forceinline__ void ldsm_x4(uint32_t& r0, uint32_t& r1,
                                        uint32_t& r2, uint32_t& r3,
                                        uint32_t addr) {
    asm volatile("ldmatrix.sync.aligned.m8n8.x4.shared.b16 {%0,%1,%2,%3}, [%4];"
                 : "=r"(r0), "=r"(r1), "=r"(r2), "=r"(r3) : "r"(addr));
}
__device__ __forceinline__ void mma_f16(float* d, const uint32_t* a,
                                        const uint32_t* b) {
    asm volatile(
        "mma.sync.aligned.m16n8k16.row.col.f32.f16.f16.f32 "
        "{%0,%1,%2,%3}, {%4,%5,%6,%7}, {%8,%9}, {%0,%1,%2,%3};"
        : "+f"(d[0]), "+f"(d[1]), "+f"(d[2]), "+f"(d[3])
        : "r"(a[0]), "r"(a[1]), "r"(a[2]), "r"(a[3]), "r"(b[0]), "r"(b[1]));
}
// fp32 pair -> fp16 hi + fp16 lo (residual), packed as half2 words
__device__ __forceinline__ void split2h(float x, float y,
                                        uint32_t& hi, uint32_t& lo) {
    __half2 h = __floats2half2_rn(x, y);
    float rx = x - __half2float(__low2half(h));
    float ry = y - __half2float(__high2half(h));
    __half2 l = __floats2half2_rn(rx, ry);
    hi = *(uint32_t*)&h;
    lo = *(uint32_t*)&l;
}
__device__ __forceinline__ void cp16(uint32_t smem, const void* gmem) {
    asm volatile("cp.async.cg.shared.global [%0], [%1], 16;"
                 :: "r"(smem), "l"(gmem));
}
#define CP_COMMIT() asm volatile("cp.async.commit_group;" ::: "memory")
#define CP_WAIT(n)  asm volatile("cp.async.wait_group %0;" :: "n"(n) : "memory")

// ============================================================================
// prep_all: one launch — split x to hi/lo fp16, round both weights to fp16.
// ============================================================================
#define XN4  (BATCH * SEQ * DIM / 4)
#define WQ4  (QKVD * DIM / 4)
#define WO4  (DIM * DIM / 4)

__global__ void prep_all(const float* __restrict__ x,
                         const float* __restrict__ wq,
                         const float* __restrict__ wo,
                         __half* __restrict__ xh, __half* __restrict__ xl,
                         __half* __restrict__ wqh, __half* __restrict__ woh) {
    const int stride = gridDim.x * blockDim.x;
    const int base = blockIdx.x * blockDim.x + threadIdx.x;
    for (int i = base; i < XN4; i += stride) {
        float4 v = ((const float4*)x)[i];
        uint2 h, l;
        split2h(v.x, v.y, h.x, l.x);
        split2h(v.z, v.w, h.y, l.y);
        ((uint2*)xh)[i] = h;
        ((uint2*)xl)[i] = l;
    }
    for (int i = base; i < WQ4; i += stride) {
        float4 v = ((const float4*)wq)[i];
        __half2 h0 = __floats2half2_rn(v.x, v.y);
        __half2 h1 = __floats2half2_rn(v.z, v.w);
        uint2 h; h.x = *(uint32_t*)&h0; h.y = *(uint32_t*)&h1;
        ((uint2*)wqh)[i] = h;
    }
    for (int i = base; i < WO4; i += stride) {
        float4 v = ((const float4*)wo)[i];
        __half2 h0 = __floats2half2_rn(v.x, v.y);
        __half2 h1 = __floats2half2_rn(v.z, v.w);
        uint2 h; h.x = *(uint32_t*)&h0; h.y = *(uint32_t*)&h1;
        ((uint2*)woh)[i] = h;
    }
}

// ============================================================================
// fp16x2 GEMM (split-A only):  C = (Ah+Al) @ Bh^T + bias
// CTA tile 128x128, K-chunk 64, 2-stage cp.async, 8 warps (4m x 2n),
// warp tile 32x64, 2 CTAs/SM.  (At the legacy-HMMA roofline — frozen.)
// ============================================================================
#define GKC    64
#define GPITCH 72
#define GA_TILE (128 * GPITCH * 2)
#define GB_TILE (128 * GPITCH * 2)
#define GSTAGE_B (2 * GA_TILE + GB_TILE)
#define G_SMEM_BYTES (2 * GSTAGE_B)

__global__ __launch_bounds__(256, 2) void gemm_f16(
    int M, int N_, int K,
    const __half* __restrict__ Ah, const __half* __restrict__ Al,
    const __half* __restrict__ Bh,
    const float* __restrict__ bias,
    float* __restrict__ C,
    __half* __restrict__ Ch, __half* __restrict__ Cl)
{
    extern __shared__ __align__(16) char sm[];
    const uint32_t sb0 = smem_u32(sm);

    const int tid = threadIdx.x;
    const int wid = tid >> 5;
    const int lane = tid & 31;
    const int n0 = blockIdx.x * 128;
    const int m0 = blockIdx.y * 128;
    const int warp_m = wid & 3;
    const int warp_n = wid >> 2;

    float acc[2][8][4];
#pragma unroll
    for (int mt = 0; mt < 2; mt++)
#pragma unroll
        for (int nt = 0; nt < 8; nt++)
#pragma unroll
            for (int r = 0; r < 4; r++) acc[mt][nt][r] = 0.0f;

    const int a_row = warp_m * 32 + (lane & 7) + ((lane >> 3) & 1) * 8;
    const int a_kof = ((lane >> 4) & 1) * 8;
    const int b_row = warp_n * 64 + (lane & 7) + ((lane >> 4) & 1) * 8;
    const int b_kof = ((lane >> 3) & 1) * 8;

    const int nchunk = K / GKC;

    auto issue_chunk = [&](int ic, int s) {
        const uint32_t sb = sb0 + (uint32_t)s * GSTAGE_B;
        const int kc = ic * GKC;
#pragma unroll
        for (int i = 0; i < 4; i++) {
            const int id = tid + 256 * i;
            const int row = id >> 3;
            const int c8 = (id & 7) * 8;
            const uint32_t so = (uint32_t)(row * GPITCH + c8) * 2;
            const size_t ga = (size_t)(m0 + row) * K + kc + c8;
            const size_t gb = (size_t)(n0 + row) * K + kc + c8;
            cp16(sb + so,               Ah + ga);
            cp16(sb + GA_TILE + so,     Al + ga);
            cp16(sb + 2 * GA_TILE + so, Bh + gb);
        }
    };

    issue_chunk(0, 0); CP_COMMIT();

    for (int ic = 0; ic < nchunk; ic++) {
        if (ic + 1 < nchunk) {
            issue_chunk(ic + 1, (ic + 1) & 1); CP_COMMIT();
            CP_WAIT(1);
        } else {
            CP_WAIT(0);
        }
        __syncthreads();

        const uint32_t sb  = sb0 + (uint32_t)(ic & 1) * GSTAGE_B;
        const uint32_t sAh = sb;
        const uint32_t sAl = sb + GA_TILE;
        const uint32_t sBh = sb + 2 * GA_TILE;

#pragma unroll
        for (int ks = 0; ks < 4; ks++) {
            const int k16 = ks * 16;
            uint32_t ah[2][4], al[2][4];
#pragma unroll
            for (int mt = 0; mt < 2; mt++) {
                const uint32_t aoff =
                    (uint32_t)((a_row + mt * 16) * GPITCH + k16 + a_kof) * 2;
                ldsm_x4(ah[mt][0], ah[mt][1], ah[mt][2], ah[mt][3], sAh + aoff);
                ldsm_x4(al[mt][0], al[mt][1], al[mt][2], al[mt][3], sAl + aoff);
            }
            uint32_t bh[8][2];
#pragma unroll
            for (int ntp = 0; ntp < 4; ntp++) {
                const uint32_t boff =
                    (uint32_t)((b_row + ntp * 16) * GPITCH + k16 + b_kof) * 2;
                ldsm_x4(bh[2 * ntp][0], bh[2 * ntp][1],
                        bh[2 * ntp + 1][0], bh[2 * ntp + 1][1], sBh + boff);
            }
#pragma unroll
            for (int mt = 0; mt < 2; mt++)
#pragma unroll
                for (int nt = 0; nt < 8; nt++)
                    mma_f16(acc[mt][nt], ah[mt], bh[nt]);
#pragma unroll
            for (int mt = 0; mt < 2; mt++)
#pragma unroll
                for (int nt = 0; nt < 8; nt++)
                    mma_f16(acc[mt][nt], al[mt], bh[nt]);
        }
        __syncthreads();
    }

    // Epilogue
    const int er0 = m0 + warp_m * 32 + (lane >> 2);
    const int ec0 = n0 + warp_n * 64 + (lane & 3) * 2;
#pragma unroll
    for (int mt = 0; mt < 2; mt++) {
#pragma unroll
        for (int nt = 0; nt < 8; nt++) {
            const int col = ec0 + nt * 8;
            const float bx = bias[col], by = bias[col + 1];
            const size_t o0 = (size_t)(er0 + mt * 16) * N_ + col;
            const size_t o1 = (size_t)(er0 + mt * 16 + 8) * N_ + col;
            const float c00 = acc[mt][nt][0] + bx, c01 = acc[mt][nt][1] + by;
            const float c10 = acc[mt][nt][2] + bx, c11 = acc[mt][nt][3] + by;
            if (C) {
                *(float2*)(C + o0) = make_float2(c00, c01);
                *(float2*)(C + o1) = make_float2(c10, c11);
            } else {
                uint32_t h0, l0w, h1, l1w;
                split2h(c00, c01, h0, l0w);
                split2h(c10, c11, h1, l1w);
                *(uint32_t*)(Ch + o0) = h0;  *(uint32_t*)(Cl + o0) = l0w;
                *(uint32_t*)(Ch + o1) = h1;  *(uint32_t*)(Cl + o1) = l1w;
            }
        }
    }
}

// ============================================================================
// Flash attention, tensor cores, fp16 split-A scheme.
// R12: software-pipelined K (double-buffered cp.async, in-flight during
// compute) and V (register prefetch of next tile, STS at top of next iter).
// smem: Qh,Ql [128][72]; Kh x2 [64][72]; Vth [64][72]
// ============================================================================
#define APITCH 72
#define A_QTILE (128 * APITCH * 2)     // 18432
#define A_KBUF  (64 * APITCH * 2)      //  9216
#define A_SMEM_BYTES (2 * A_QTILE + 3 * A_KBUF)   // 64512

__global__ __launch_bounds__(256, 1) void attn_tc(
    const __half* __restrict__ qkvh,
    const __half* __restrict__ qkvl,
    __half* __restrict__ aoh,
    __half* __restrict__ aol)
{
    extern __shared__ __align__(16) char smema[];
    const uint32_t sQh  = smem_u32(smema);
    const uint32_t sQl  = sQh + A_QTILE;
    const uint32_t sKh0 = sQl + A_QTILE;
    const uint32_t sKh1 = sKh0 + A_KBUF;
    const uint32_t sVth = sKh1 + A_KBUF;
    __half* pVth = (__half*)(smema + 2 * A_QTILE + 2 * A_KBUF);

    const int qt = gridDim.x - 1 - blockIdx.x;   // heavy tiles first
    const int h  = blockIdx.y;
    const int b  = blockIdx.z;
    const int tid = threadIdx.x;
    const int wid = tid >> 5;
    const int lane = tid & 31;

    const size_t bN = (size_t)b * SEQ;
    const int qcol = h * HD;
    const int kcol = DIM + h * HD;
    const int vcol = 2 * DIM + h * HD;
    const int ntiles = (qt + 1) * 2;

    // V prefetch mapping: thread owns key vrr, dims [vd0, vd0+16)
    const int vrr = tid >> 2;
    const int vd0 = (tid & 3) * 16;

    // K loader into a given buffer
    auto issue_k = [&](int kt, uint32_t kbuf) {
        const int kb = kt * 64;
#pragma unroll
        for (int i = 0; i < 2; i++) {
            const int id = tid + 256 * i;
            const int row = id >> 3;
            const int c8 = (id & 7) * 8;
            const uint32_t so = (uint32_t)(row * APITCH + c8) * 2;
            const size_t g = (bN + kb + row) * QKVD + kcol + c8;
            cp16(kbuf + so, qkvh + g);
        }
    };

    // ---- Q tile (cp.async) + K(0) (cp.async) + V(0) (register prefetch) ----
#pragma unroll
    for (int i = 0; i < 4; i++) {
        const int id = tid + 256 * i;
        const int row = id >> 3;
        const int c8 = (id & 7) * 8;
        const uint32_t so = (uint32_t)(row * APITCH + c8) * 2;
        const size_t g = (bN + qt * 128 + row) * QKVD + qcol + c8;
        cp16(sQh + so, qkvh + g);
        cp16(sQl + so, qkvl + g);
    }
    CP_COMMIT();
    issue_k(0, sKh0);
    CP_COMMIT();

    uint4 va, vb;
    {
        const size_t g = (bN + vrr) * QKVD + vcol + vd0;
        va = *(const uint4*)(qkvh + g);
        vb = *(const uint4*)(qkvh + g + 8);
    }

    CP_WAIT(1);            // Q done; K(0) may still be in flight
    __syncthreads();

    // ---- Hoist Q fragments ----
    const int a_row = wid * 16 + (lane & 7) + ((lane >> 3) & 1) * 8;
    const int a_kof = ((lane >> 4) & 1) * 8;
    uint32_t qh[4][4], ql[4][4];
#pragma unroll
    for (int ks = 0; ks < 4; ks++) {
        const uint32_t off = (uint32_t)(a_row * APITCH + ks * 16 + a_kof) * 2;
        ldsm_x4(qh[ks][0], qh[ks][1], qh[ks][2], qh[ks][3], sQh + off);
        ldsm_x4(ql[ks][0], ql[ks][1], ql[ks][2], ql[ks][3], sQl + off);
    }

    const int b_row = (lane & 7) + ((lane >> 4) & 1) * 8;
    const int b_kof = ((lane >> 3) & 1) * 8;

    float o[8][4];
#pragma unroll
    for (int nt = 0; nt < 8; nt++)
#pragma unroll
        for (int r = 0; r < 4; r++) o[nt][r] = 0.0f;
    float m0 = -1e30f, m1 = -1e30f, l0 = 0.0f, l1 = 0.0f;

    const float scale = 0.125f;
    const int row_lo = qt * 128 + wid * 16 + (lane >> 2);
    const int row_hi = row_lo + 8;

    for (int kt = 0; kt < ntiles; kt++) {
        const int kb = kt * 64;
        const uint32_t sKcur = (kt & 1) ? sKh1 : sKh0;
        const bool have_next = (kt + 1 < ntiles);

        // Issue K(kt+1) into the other buffer (in flight during compute)
        if (have_next) {
            issue_k(kt + 1, (kt & 1) ? sKh0 : sKh1);
            CP_COMMIT();
        }

        // Store V(kt) (prefetched last iteration) to smem, transposed
        {
            union { uint4 q; __half e[8]; } u0, u1;
            u0.q = va; u1.q = vb;
#pragma unroll
            for (int e = 0; e < 8; e++) {
                pVth[(vd0 + e) * APITCH + vrr]     = u0.e[e];
                pVth[(vd0 + 8 + e) * APITCH + vrr] = u1.e[e];
            }
        }
        // Prefetch V(kt+1) into registers (LDG overlaps compute below)
        uint4 va2 = va, vb2 = vb;
        if (have_next) {
            const size_t g = (bN + kb + 64 + vrr) * QKVD + vcol + vd0;
            va2 = *(const uint4*)(qkvh + g);
            vb2 = *(const uint4*)(qkvh + g + 8);
        }

        if (have_next) { CP_WAIT(1); } else { CP_WAIT(0); }
        __syncthreads();

        // ---- S = Q @ K^T ----
        float s[8][4];
#pragma unroll
        for (int nt = 0; nt < 8; nt++)
#pragma unroll
            for (int r = 0; r < 4; r++) s[nt][r] = 0.0f;

#pragma unroll
        for (int ks = 0; ks < 4; ks++) {
            uint32_t kh[8][2];
#pragma unroll
            for (int ntp = 0; ntp < 4; ntp++) {
                const uint32_t off =
                    (uint32_t)((ntp * 16 + b_row) * APITCH + ks * 16 + b_kof) * 2;
                ldsm_x4(kh[2 * ntp][0], kh[2 * ntp][1],
                        kh[2 * ntp + 1][0], kh[2 * ntp + 1][1], sKcur + off);
            }
#pragma unroll
            for (int nt = 0; nt < 8; nt++) mma_f16(s[nt], qh[ks], kh[nt]);
#pragma unroll
            for (int nt = 0; nt < 8; nt++) mma_f16(s[nt], ql[ks], kh[nt]);
        }

        // ---- Scale + causal mask ----
        const bool full = (kb + 63) <= qt * 128;
        if (full) {
#pragma unroll
            for (int nt = 0; nt < 8; nt++)
#pragma unroll
                for (int r = 0; r < 4; r++) s[nt][r] *= scale;
        } else {
#pragma unroll
            for (int nt = 0; nt < 8; nt++) {
                const int col = kb + nt * 8 + (lane & 3) * 2;
                s[nt][0] = (col     <= row_lo) ? s[nt][0] * scale : -1e30f;
                s[nt][1] = (col + 1 <= row_lo) ? s[nt][1] * scale : -1e30f;
                s[nt][2] = (col     <= row_hi) ? s[nt][2] * scale : -1e30f;
                s[nt][3] = (col + 1 <= row_hi) ? s[nt][3] * scale : -1e30f;
            }
        }

        // ---- Online softmax ----
        float tm0 = -1e30f, tm1 = -1e30f;
#pragma unroll
        for (int nt = 0; nt < 8; nt++) {
            tm0 = fmaxf(tm0, fmaxf(s[nt][0], s[nt][1]));
            tm1 = fmaxf(tm1, fmaxf(s[nt][2], s[nt][3]));
        }
        tm0 = fmaxf(tm0, __shfl_xor_sync(0xffffffffu, tm0, 1));
        tm0 = fmaxf(tm0, __shfl_xor_sync(0xffffffffu, tm0, 2));
        tm1 = fmaxf(tm1, __shfl_xor_sync(0xffffffffu, tm1, 1));
        tm1 = fmaxf(tm1, __shfl_xor_sync(0xffffffffu, tm1, 2));

        const float nm0 = fmaxf(m0, tm0);
        const float nm1 = fmaxf(m1, tm1);
        const float corr0 = __expf(m0 - nm0);
        const float corr1 = __expf(m1 - nm1);

        float ps0 = 0.0f, ps1 = 0.0f;
#pragma unroll
        for (int nt = 0; nt < 8; nt++) {
            s[nt][0] = __expf(s[nt][0] - nm0); ps0 += s[nt][0];
            s[nt][1] = __expf(s[nt][1] - nm0); ps0 += s[nt][1];
            s[nt][2] = __expf(s[nt][2] - nm1); ps1 += s[nt][2];
            s[nt][3] = __expf(s[nt][3] - nm1); ps1 += s[nt][3];
        }
        ps0 += __shfl_xor_sync(0xffffffffu, ps0, 1);
        ps0 += __shfl_xor_sync(0xffffffffu, ps0, 2);
        ps1 += __shfl_xor_sync(0xffffffffu, ps1, 1);
        ps1 += __shfl_xor_sync(0xffffffffu, ps1, 2);

        l0 = l0 * corr0 + ps0; m0 = nm0;
        l1 = l1 * corr1 + ps1; m1 = nm1;
#pragma unroll
        for (int nt = 0; nt < 8; nt++) {
            o[nt][0] *= corr0; o[nt][1] *= corr0;
            o[nt][2] *= corr1; o[nt][3] *= corr1;
        }

        // ---- O += P @ V (P repack fp16-split, 2 product passes) ----
        uint32_t pah[4][4], pal[4][4], vh[4][8][2];
#pragma unroll
        for (int ks = 0; ks < 4; ks++) {
            const int j = 2 * ks;
            split2h(s[j][0],     s[j][1],     pah[ks][0], pal[ks][0]);
            split2h(s[j][2],     s[j][3],     pah[ks][1], pal[ks][1]);
            split2h(s[j + 1][0], s[j + 1][1], pah[ks][2], pal[ks][2]);
            split2h(s[j + 1][2], s[j + 1][3], pah[ks][3], pal[ks][3]);
#pragma unroll
            for (int ntp = 0; ntp < 4; ntp++) {
                const uint32_t off =
                    (uint32_t)((ntp * 16 + b_row) * APITCH + ks * 16 + b_kof) * 2;
                ldsm_x4(vh[ks][2 * ntp][0], vh[ks][2 * ntp][1],
                        vh[ks][2 * ntp + 1][0], vh[ks][2 * ntp + 1][1], sVth + off);
            }
        }
#pragma unroll
        for (int ks = 0; ks < 4; ks++)
#pragma unroll
            for (int nt = 0; nt < 8; nt++) mma_f16(o[nt], pah[ks], vh[ks][nt]);
#pragma unroll
        for (int ks = 0; ks < 4; ks++)
#pragma unroll
            for (int nt = 0; nt < 8; nt++) mma_f16(o[nt], pal[ks], vh[ks][nt]);
        __syncthreads();   // protects Vth + K buffer reuse next iteration

        va = va2; vb = vb2;
    }

    // ---- Epilogue: normalize + split-store to aoh/aol ----
    const float inv0 = 1.0f / l0;
    const float inv1 = 1.0f / l1;
#pragma unroll
    for (int nt = 0; nt < 8; nt++) {
        const int col = h * HD + nt * 8 + (lane & 3) * 2;
        const size_t o0 = (bN + row_lo) * DIM + col;
        const size_t o1 = (bN + row_hi) * DIM + col;
        uint32_t h0, l0w, h1, l1w;
        split2h(o[nt][0] * inv0, o[nt][1] * inv0, h0, l0w);
        split2h(o[nt][2] * inv1, o[nt][3] * inv1, h1, l1w);
        *(uint32_t*)(aoh + o0) = h0;  *(uint32_t*)(aol + o0) = l0w;
        *(uint32_t*)(aoh + o1) = h1;  *(uint32_t*)(aol + o1) = l1w;
    }
}

// ---------------------------------------------------------------------------
extern "C" void kernel_launch(void* const* d_in, const int* in_sizes, int n_in,
                              void* d_out, int out_size)
{
    const float* x     = (const float*)d_in[0];
    const float* W_qkv = (const float*)d_in[1];
    const float* b_qkv = (const float*)d_in[2];
    const float* W_out = (const float*)d_in[3];
    const float* b_out = (const float*)d_in[4];
    float* out = (float*)d_out;

    __half *xh, *xl, *wqh, *woh, *qkvh, *qkvl, *aoh, *aol;
    cudaGetSymbolAddress((void**)&xh,  g_xh);   cudaGetSymbolAddress((void**)&xl,  g_xl);
    cudaGetSymbolAddress((void**)&wqh, g_wqh);  cudaGetSymbolAddress((void**)&woh, g_woh);
    cudaGetSymbolAddress((void**)&qkvh, g_qkvh); cudaGetSymbolAddress((void**)&qkvl, g_qkvl);
    cudaGetSymbolAddress((void**)&aoh, g_aoh);  cudaGetSymbolAddress((void**)&aol, g_aol);

    cudaFuncSetAttribute(gemm_f16,
                         cudaFuncAttributeMaxDynamicSharedMemorySize, G_SMEM_BYTES);
    cudaFuncSetAttribute(attn_tc,
                         cudaFuncAttributeMaxDynamicSharedMemorySize, A_SMEM_BYTES);

    const int M = BATCH * SEQ;  // 4096

    // 0) One-launch prep: split x; round weights
    prep_all<<<592, 256>>>(x, W_qkv, W_out, xh, xl, wqh, woh);

    // 1) QKV projection -> split fp16 qkv
    {
        dim3 grid(QKVD / 128, M / 128);
        gemm_f16<<<grid, 256, G_SMEM_BYTES>>>(M, QKVD, DIM, xh, xl, wqh,
                                              b_qkv, nullptr, qkvh, qkvl);
    }
    // 2) Attention -> split fp16 aout
    {
        dim3 grid(SEQ / 128, HEADS, BATCH);
        attn_tc<<<grid, 256, A_SMEM_BYTES>>>(qkvh, qkvl, aoh, aol);
    }
    // 3) Output projection -> fp32 out
    {
        dim3 grid(DIM / 128, M / 128);
        gemm_f16<<<grid, 256, G_SMEM_BYTES>>>(M, DIM, DIM, aoh, aol, woh,
                                              b_out, out, nullptr, nullptr);
    }
}

// round 13
// speedup vs baseline: 1.6011x; 1.0395x over previous
#include <cuda_runtime.h>
#include <cuda_fp16.h>
#include <math.h>
#include <stdint.h>

// Problem constants
#define BATCH 2
#define SEQ   2048
#define DIM   1024
#define HEADS 16
#define HD    64
#define QKVD  3072   // 3*DIM

// ---------------------------------------------------------------------------
// Global scratch (alloc-free rule). hi/lo fp16 pairs represent fp32 (A-side);
// B-side operands are single fp16 (one rounding, 2^-12 rel).
// ---------------------------------------------------------------------------
__device__ __half g_xh [(size_t)BATCH * SEQ * DIM];
__device__ __half g_xl [(size_t)BATCH * SEQ * DIM];
__device__ __half g_wqh[(size_t)QKVD * DIM];
__device__ __half g_woh[(size_t)DIM * DIM];
__device__ __half g_qkvh[(size_t)BATCH * SEQ * QKVD];
__device__ __half g_qkvl[(size_t)BATCH * SEQ * QKVD];
__device__ __half g_aoh[(size_t)BATCH * SEQ * DIM];
__device__ __half g_aol[(size_t)BATCH * SEQ * DIM];

// ============================================================================
// Helpers (generic PTX, compute_103-safe)
// ============================================================================
__device__ __forceinline__ uint32_t smem_u32(const void* p) {
    uint32_t a;
    asm("{ .reg .u64 t; cvta.to.shared.u64 t, %1; cvt.u32.u64 %0, t; }"
        : "=r"(a) : "l"(p));
    return a;
}
__device__ __forceinline__ void ldsm_x4(uint32_t& r0, uint32_t& r1,
                                        uint32_t& r2, uint32_t& r3,
                                        uint32_t addr) {
    asm volatile("ldmatrix.sync.aligned.m8n8.x4.shared.b16 {%0,%1,%2,%3}, [%4];"
                 : "=r"(r0), "=r"(r1), "=r"(r2), "=r"(r3) : "r"(addr));
}
__device__ __forceinline__ void mma_f16(float* d, const uint32_t* a,
                                        const uint32_t* b) {
    asm volatile(
        "mma.sync.aligned.m16n8k16.row.col.f32.f16.f16.f32 "
        "{%0,%1,%2,%3}, {%4,%5,%6,%7}, {%8,%9}, {%0,%1,%2,%3};"
        : "+f"(d[0]), "+f"(d[1]), "+f"(d[2]), "+f"(d[3])
        : "r"(a[0]), "r"(a[1]), "r"(a[2]), "r"(a[3]), "r"(b[0]), "r"(b[1]));
}
// fp32 pair -> fp16 hi + fp16 lo (residual), packed as half2 words
__device__ __forceinline__ void split2h(float x, float y,
                                        uint32_t& hi, uint32_t& lo) {
    __half2 h = __floats2half2_rn(x, y);
    float rx = x - __half2float(__low2half(h));
    float ry = y - __half2float(__high2half(h));
    __half2 l = __floats2half2_rn(rx, ry);
    hi = *(uint32_t*)&h;
    lo = *(uint32_t*)&l;
}
__device__ __forceinline__ uint32_t pack2h(float x, float y) {
    __half2 h = __floats2half2_rn(x, y);
    return *(uint32_t*)&h;
}
__device__ __forceinline__ void cp16(uint32_t smem, const void* gmem) {
    asm volatile("cp.async.cg.shared.global [%0], [%1], 16;"
                 :: "r"(smem), "l"(gmem));
}
#define CP_COMMIT() asm volatile("cp.async.commit_group;" ::: "memory")
#define CP_WAIT(n)  asm volatile("cp.async.wait_group %0;" :: "n"(n) : "memory")

// ============================================================================
// prep_all: one launch — split x to hi/lo fp16, round both weights to fp16.
// ============================================================================
#define XN4  (BATCH * SEQ * DIM / 4)
#define WQ4  (QKVD * DIM / 4)
#define WO4  (DIM * DIM / 4)

__global__ void prep_all(const float* __restrict__ x,
                         const float* __restrict__ wq,
                         const float* __restrict__ wo,
                         __half* __restrict__ xh, __half* __restrict__ xl,
                         __half* __restrict__ wqh, __half* __restrict__ woh) {
    const int stride = gridDim.x * blockDim.x;
    const int base = blockIdx.x * blockDim.x + threadIdx.x;
    for (int i = base; i < XN4; i += stride) {
        float4 v = ((const float4*)x)[i];
        uint2 h, l;
        split2h(v.x, v.y, h.x, l.x);
        split2h(v.z, v.w, h.y, l.y);
        ((uint2*)xh)[i] = h;
        ((uint2*)xl)[i] = l;
    }
    for (int i = base; i < WQ4; i += stride) {
        float4 v = ((const float4*)wq)[i];
        uint2 h;
        h.x = pack2h(v.x, v.y);
        h.y = pack2h(v.z, v.w);
        ((uint2*)wqh)[i] = h;
    }
    for (int i = base; i < WO4; i += stride) {
        float4 v = ((const float4*)wo)[i];
        uint2 h;
        h.x = pack2h(v.x, v.y);
        h.y = pack2h(v.z, v.w);
        ((uint2*)woh)[i] = h;
    }
}

// ============================================================================
// fp16x2 GEMM (split-A only):  C = (Ah+Al) @ Bh^T + bias
// CTA tile 128x128, K-chunk 64, 2-stage cp.async, 8 warps (4m x 2n),
// warp tile 32x64, 2 CTAs/SM.  (At the legacy-HMMA roofline — frozen.)
// ============================================================================
#define GKC    64
#define GPITCH 72
#define GA_TILE (128 * GPITCH * 2)
#define GB_TILE (128 * GPITCH * 2)
#define GSTAGE_B (2 * GA_TILE + GB_TILE)
#define G_SMEM_BYTES (2 * GSTAGE_B)

__global__ __launch_bounds__(256, 2) void gemm_f16(
    int M, int N_, int K,
    const __half* __restrict__ Ah, const __half* __restrict__ Al,
    const __half* __restrict__ Bh,
    const float* __restrict__ bias,
    float* __restrict__ C,
    __half* __restrict__ Ch, __half* __restrict__ Cl)
{
    extern __shared__ __align__(16) char sm[];
    const uint32_t sb0 = smem_u32(sm);

    const int tid = threadIdx.x;
    const int wid = tid >> 5;
    const int lane = tid & 31;
    const int n0 = blockIdx.x * 128;
    const int m0 = blockIdx.y * 128;
    const int warp_m = wid & 3;
    const int warp_n = wid >> 2;

    float acc[2][8][4];
#pragma unroll
    for (int mt = 0; mt < 2; mt++)
#pragma unroll
        for (int nt = 0; nt < 8; nt++)
#pragma unroll
            for (int r = 0; r < 4; r++) acc[mt][nt][r] = 0.0f;

    const int a_row = warp_m * 32 + (lane & 7) + ((lane >> 3) & 1) * 8;
    const int a_kof = ((lane >> 4) & 1) * 8;
    const int b_row = warp_n * 64 + (lane & 7) + ((lane >> 4) & 1) * 8;
    const int b_kof = ((lane >> 3) & 1) * 8;

    const int nchunk = K / GKC;

    auto issue_chunk = [&](int ic, int s) {
        const uint32_t sb = sb0 + (uint32_t)s * GSTAGE_B;
        const int kc = ic * GKC;
#pragma unroll
        for (int i = 0; i < 4; i++) {
            const int id = tid + 256 * i;
            const int row = id >> 3;
            const int c8 = (id & 7) * 8;
            const uint32_t so = (uint32_t)(row * GPITCH + c8) * 2;
            const size_t ga = (size_t)(m0 + row) * K + kc + c8;
            const size_t gb = (size_t)(n0 + row) * K + kc + c8;
            cp16(sb + so,               Ah + ga);
            cp16(sb + GA_TILE + so,     Al + ga);
            cp16(sb + 2 * GA_TILE + so, Bh + gb);
        }
    };

    issue_chunk(0, 0); CP_COMMIT();

    for (int ic = 0; ic < nchunk; ic++) {
        if (ic + 1 < nchunk) {
            issue_chunk(ic + 1, (ic + 1) & 1); CP_COMMIT();
            CP_WAIT(1);
        } else {
            CP_WAIT(0);
        }
        __syncthreads();

        const uint32_t sb  = sb0 + (uint32_t)(ic & 1) * GSTAGE_B;
        const uint32_t sAh = sb;
        const uint32_t sAl = sb + GA_TILE;
        const uint32_t sBh = sb + 2 * GA_TILE;

#pragma unroll
        for (int ks = 0; ks < 4; ks++) {
            const int k16 = ks * 16;
            uint32_t ah[2][4], al[2][4];
#pragma unroll
            for (int mt = 0; mt < 2; mt++) {
                const uint32_t aoff =
                    (uint32_t)((a_row + mt * 16) * GPITCH + k16 + a_kof) * 2;
                ldsm_x4(ah[mt][0], ah[mt][1], ah[mt][2], ah[mt][3], sAh + aoff);
                ldsm_x4(al[mt][0], al[mt][1], al[mt][2], al[mt][3], sAl + aoff);
            }
            uint32_t bh[8][2];
#pragma unroll
            for (int ntp = 0; ntp < 4; ntp++) {
                const uint32_t boff =
                    (uint32_t)((b_row + ntp * 16) * GPITCH + k16 + b_kof) * 2;
                ldsm_x4(bh[2 * ntp][0], bh[2 * ntp][1],
                        bh[2 * ntp + 1][0], bh[2 * ntp + 1][1], sBh + boff);
            }
#pragma unroll
            for (int mt = 0; mt < 2; mt++)
#pragma unroll
                for (int nt = 0; nt < 8; nt++)
                    mma_f16(acc[mt][nt], ah[mt], bh[nt]);
#pragma unroll
            for (int mt = 0; mt < 2; mt++)
#pragma unroll
                for (int nt = 0; nt < 8; nt++)
                    mma_f16(acc[mt][nt], al[mt], bh[nt]);
        }
        __syncthreads();
    }

    // Epilogue
    const int er0 = m0 + warp_m * 32 + (lane >> 2);
    const int ec0 = n0 + warp_n * 64 + (lane & 3) * 2;
#pragma unroll
    for (int mt = 0; mt < 2; mt++) {
#pragma unroll
        for (int nt = 0; nt < 8; nt++) {
            const int col = ec0 + nt * 8;
            const float bx = bias[col], by = bias[col + 1];
            const size_t o0 = (size_t)(er0 + mt * 16) * N_ + col;
            const size_t o1 = (size_t)(er0 + mt * 16 + 8) * N_ + col;
            const float c00 = acc[mt][nt][0] + bx, c01 = acc[mt][nt][1] + by;
            const float c10 = acc[mt][nt][2] + bx, c11 = acc[mt][nt][3] + by;
            if (C) {
                *(float2*)(C + o0) = make_float2(c00, c01);
                *(float2*)(C + o1) = make_float2(c10, c11);
            } else {
                uint32_t h0, l0w, h1, l1w;
                split2h(c00, c01, h0, l0w);
                split2h(c10, c11, h1, l1w);
                *(uint32_t*)(Ch + o0) = h0;  *(uint32_t*)(Cl + o0) = l0w;
                *(uint32_t*)(Ch + o1) = h1;  *(uint32_t*)(Cl + o1) = l1w;
            }
        }
    }
}

// ============================================================================
// Flash attention, tensor cores.
// Q split hi/lo (2-product S); K, V, and now P single fp16 (1-product PV).
// K double-buffered cp.async; V register-prefetch pipeline (R12).
// smem: Qh,Ql [128][72]; Kh x2 [64][72]; Vth [64][72]
// ============================================================================
#define APITCH 72
#define A_QTILE (128 * APITCH * 2)     // 18432
#define A_KBUF  (64 * APITCH * 2)      //  9216
#define A_SMEM_BYTES (2 * A_QTILE + 3 * A_KBUF)   // 64512

__global__ __launch_bounds__(256, 1) void attn_tc(
    const __half* __restrict__ qkvh,
    const __half* __restrict__ qkvl,
    __half* __restrict__ aoh,
    __half* __restrict__ aol)
{
    extern __shared__ __align__(16) char smema[];
    const uint32_t sQh  = smem_u32(smema);
    const uint32_t sQl  = sQh + A_QTILE;
    const uint32_t sKh0 = sQl + A_QTILE;
    const uint32_t sKh1 = sKh0 + A_KBUF;
    const uint32_t sVth = sKh1 + A_KBUF;
    __half* pVth = (__half*)(smema + 2 * A_QTILE + 2 * A_KBUF);

    const int qt = gridDim.x - 1 - blockIdx.x;   // heavy tiles first
    const int h  = blockIdx.y;
    const int b  = blockIdx.z;
    const int tid = threadIdx.x;
    const int wid = tid >> 5;
    const int lane = tid & 31;

    const size_t bN = (size_t)b * SEQ;
    const int qcol = h * HD;
    const int kcol = DIM + h * HD;
    const int vcol = 2 * DIM + h * HD;
    const int ntiles = (qt + 1) * 2;

    const int vrr = tid >> 2;
    const int vd0 = (tid & 3) * 16;

    auto issue_k = [&](int kt, uint32_t kbuf) {
        const int kb = kt * 64;
#pragma unroll
        for (int i = 0; i < 2; i++) {
            const int id = tid + 256 * i;
            const int row = id >> 3;
            const int c8 = (id & 7) * 8;
            const uint32_t so = (uint32_t)(row * APITCH + c8) * 2;
            const size_t g = (bN + kb + row) * QKVD + kcol + c8;
            cp16(kbuf + so, qkvh + g);
        }
    };

    // ---- Q tile (cp.async) + K(0) (cp.async) + V(0) (register prefetch) ----
#pragma unroll
    for (int i = 0; i < 4; i++) {
        const int id = tid + 256 * i;
        const int row = id >> 3;
        const int c8 = (id & 7) * 8;
        const uint32_t so = (uint32_t)(row * APITCH + c8) * 2;
        const size_t g = (bN + qt * 128 + row) * QKVD + qcol + c8;
        cp16(sQh + so, qkvh + g);
        cp16(sQl + so, qkvl + g);
    }
    CP_COMMIT();
    issue_k(0, sKh0);
    CP_COMMIT();

    uint4 va, vb;
    {
        const size_t g = (bN + vrr) * QKVD + vcol + vd0;
        va = *(const uint4*)(qkvh + g);
        vb = *(const uint4*)(qkvh + g + 8);
    }

    CP_WAIT(1);
    __syncthreads();

    // ---- Hoist Q fragments ----
    const int a_row = wid * 16 + (lane & 7) + ((lane >> 3) & 1) * 8;
    const int a_kof = ((lane >> 4) & 1) * 8;
    uint32_t qh[4][4], ql[4][4];
#pragma unroll
    for (int ks = 0; ks < 4; ks++) {
        const uint32_t off = (uint32_t)(a_row * APITCH + ks * 16 + a_kof) * 2;
        ldsm_x4(qh[ks][0], qh[ks][1], qh[ks][2], qh[ks][3], sQh + off);
        ldsm_x4(ql[ks][0], ql[ks][1], ql[ks][2], ql[ks][3], sQl + off);
    }

    const int b_row = (lane & 7) + ((lane >> 4) & 1) * 8;
    const int b_kof = ((lane >> 3) & 1) * 8;

    float o[8][4];
#pragma unroll
    for (int nt = 0; nt < 8; nt++)
#pragma unroll
        for (int r = 0; r < 4; r++) o[nt][r] = 0.0f;
    float m0 = -1e30f, m1 = -1e30f, l0 = 0.0f, l1 = 0.0f;

    const float scale = 0.125f;
    const int row_lo = qt * 128 + wid * 16 + (lane >> 2);
    const int row_hi = row_lo + 8;

    for (int kt = 0; kt < ntiles; kt++) {
        const int kb = kt * 64;
        const uint32_t sKcur = (kt & 1) ? sKh1 : sKh0;
        const bool have_next = (kt + 1 < ntiles);

        if (have_next) {
            issue_k(kt + 1, (kt & 1) ? sKh0 : sKh1);
            CP_COMMIT();
        }

        // Store V(kt) (prefetched) to smem transposed
        {
            union { uint4 q; __half e[8]; } u0, u1;
            u0.q = va; u1.q = vb;
#pragma unroll
            for (int e = 0; e < 8; e++) {
                pVth[(vd0 + e) * APITCH + vrr]     = u0.e[e];
                pVth[(vd0 + 8 + e) * APITCH + vrr] = u1.e[e];
            }
        }
        // Prefetch V(kt+1)
        uint4 va2 = va, vb2 = vb;
        if (have_next) {
            const size_t g = (bN + kb + 64 + vrr) * QKVD + vcol + vd0;
            va2 = *(const uint4*)(qkvh + g);
            vb2 = *(const uint4*)(qkvh + g + 8);
        }

        if (have_next) { CP_WAIT(1); } else { CP_WAIT(0); }
        __syncthreads();

        // ---- S = Q @ K^T (2 product passes) ----
        float s[8][4];
#pragma unroll
        for (int nt = 0; nt < 8; nt++)
#pragma unroll
            for (int r = 0; r < 4; r++) s[nt][r] = 0.0f;

#pragma unroll
        for (int ks = 0; ks < 4; ks++) {
            uint32_t kh[8][2];
#pragma unroll
            for (int ntp = 0; ntp < 4; ntp++) {
                const uint32_t off =
                    (uint32_t)((ntp * 16 + b_row) * APITCH + ks * 16 + b_kof) * 2;
                ldsm_x4(kh[2 * ntp][0], kh[2 * ntp][1],
                        kh[2 * ntp + 1][0], kh[2 * ntp + 1][1], sKcur + off);
            }
#pragma unroll
            for (int nt = 0; nt < 8; nt++) mma_f16(s[nt], qh[ks], kh[nt]);
#pragma unroll
            for (int nt = 0; nt < 8; nt++) mma_f16(s[nt], ql[ks], kh[nt]);
        }

        // ---- Scale + causal mask ----
        const bool full = (kb + 63) <= qt * 128;
        if (full) {
#pragma unroll
            for (int nt = 0; nt < 8; nt++)
#pragma unroll
                for (int r = 0; r < 4; r++) s[nt][r] *= scale;
        } else {
#pragma unroll
            for (int nt = 0; nt < 8; nt++) {
                const int col = kb + nt * 8 + (lane & 3) * 2;
                s[nt][0] = (col     <= row_lo) ? s[nt][0] * scale : -1e30f;
                s[nt][1] = (col + 1 <= row_lo) ? s[nt][1] * scale : -1e30f;
                s[nt][2] = (col     <= row_hi) ? s[nt][2] * scale : -1e30f;
                s[nt][3] = (col + 1 <= row_hi) ? s[nt][3] * scale : -1e30f;
            }
        }

        // ---- Online softmax ----
        float tm0 = -1e30f, tm1 = -1e30f;
#pragma unroll
        for (int nt = 0; nt < 8; nt++) {
            tm0 = fmaxf(tm0, fmaxf(s[nt][0], s[nt][1]));
            tm1 = fmaxf(tm1, fmaxf(s[nt][2], s[nt][3]));
        }
        tm0 = fmaxf(tm0, __shfl_xor_sync(0xffffffffu, tm0, 1));
        tm0 = fmaxf(tm0, __shfl_xor_sync(0xffffffffu, tm0, 2));
        tm1 = fmaxf(tm1, __shfl_xor_sync(0xffffffffu, tm1, 1));
        tm1 = fmaxf(tm1, __shfl_xor_sync(0xffffffffu, tm1, 2));

        const float nm0 = fmaxf(m0, tm0);
        const float nm1 = fmaxf(m1, tm1);
        const float corr0 = __expf(m0 - nm0);
        const float corr1 = __expf(m1 - nm1);

        float ps0 = 0.0f, ps1 = 0.0f;
#pragma unroll
        for (int nt = 0; nt < 8; nt++) {
            s[nt][0] = __expf(s[nt][0] - nm0); ps0 += s[nt][0];
            s[nt][1] = __expf(s[nt][1] - nm0); ps0 += s[nt][1];
            s[nt][2] = __expf(s[nt][2] - nm1); ps1 += s[nt][2];
            s[nt][3] = __expf(s[nt][3] - nm1); ps1 += s[nt][3];
        }
        ps0 += __shfl_xor_sync(0xffffffffu, ps0, 1);
        ps0 += __shfl_xor_sync(0xffffffffu, ps0, 2);
        ps1 += __shfl_xor_sync(0xffffffffu, ps1, 1);
        ps1 += __shfl_xor_sync(0xffffffffu, ps1, 2);

        l0 = l0 * corr0 + ps0; m0 = nm0;
        l1 = l1 * corr1 + ps1; m1 = nm1;
#pragma unroll
        for (int nt = 0; nt < 8; nt++) {
            o[nt][0] *= corr0; o[nt][1] *= corr0;
            o[nt][2] *= corr1; o[nt][3] *= corr1;
        }

        // ---- O += P @ V (P single fp16, ONE product pass) ----
        uint32_t pa[4][4], vh[4][8][2];
#pragma unroll
        for (int ks = 0; ks < 4; ks++) {
            const int j = 2 * ks;
            pa[ks][0] = pack2h(s[j][0],     s[j][1]);
            pa[ks][1] = pack2h(s[j][2],     s[j][3]);
            pa[ks][2] = pack2h(s[j + 1][0], s[j + 1][1]);
            pa[ks][3] = pack2h(s[j + 1][2], s[j + 1][3]);
#pragma unroll
            for (int ntp = 0; ntp < 4; ntp++) {
                const uint32_t off =
                    (uint32_t)((ntp * 16 + b_row) * APITCH + ks * 16 + b_kof) * 2;
                ldsm_x4(vh[ks][2 * ntp][0], vh[ks][2 * ntp][1],
                        vh[ks][2 * ntp + 1][0], vh[ks][2 * ntp + 1][1], sVth + off);
            }
        }
#pragma unroll
        for (int ks = 0; ks < 4; ks++)
#pragma unroll
            for (int nt = 0; nt < 8; nt++) mma_f16(o[nt], pa[ks], vh[ks][nt]);
        __syncthreads();   // protects Vth + K buffer reuse next iteration

        va = va2; vb = vb2;
    }

    // ---- Epilogue: normalize + split-store to aoh/aol ----
    const float inv0 = 1.0f / l0;
    const float inv1 = 1.0f / l1;
#pragma unroll
    for (int nt = 0; nt < 8; nt++) {
        const int col = h * HD + nt * 8 + (lane & 3) * 2;
        const size_t o0 = (bN + row_lo) * DIM + col;
        const size_t o1 = (bN + row_hi) * DIM + col;
        uint32_t h0, l0w, h1, l1w;
        split2h(o[nt][0] * inv0, o[nt][1] * inv0, h0, l0w);
        split2h(o[nt][2] * inv1, o[nt][3] * inv1, h1, l1w);
        *(uint32_t*)(aoh + o0) = h0;  *(uint32_t*)(aol + o0) = l0w;
        *(uint32_t*)(aoh + o1) = h1;  *(uint32_t*)(aol + o1) = l1w;
    }
}

// ---------------------------------------------------------------------------
extern "C" void kernel_launch(void* const* d_in, const int* in_sizes, int n_in,
                              void* d_out, int out_size)
{
    const float* x     = (const float*)d_in[0];
    const float* W_qkv = (const float*)d_in[1];
    const float* b_qkv = (const float*)d_in[2];
    const float* W_out = (const float*)d_in[3];
    const float* b_out = (const float*)d_in[4];
    float* out = (float*)d_out;

    __half *xh, *xl, *wqh, *woh, *qkvh, *qkvl, *aoh, *aol;
    cudaGetSymbolAddress((void**)&xh,  g_xh);   cudaGetSymbolAddress((void**)&xl,  g_xl);
    cudaGetSymbolAddress((void**)&wqh, g_wqh);  cudaGetSymbolAddress((void**)&woh, g_woh);
    cudaGetSymbolAddress((void**)&qkvh, g_qkvh); cudaGetSymbolAddress((void**)&qkvl, g_qkvl);
    cudaGetSymbolAddress((void**)&aoh, g_aoh);  cudaGetSymbolAddress((void**)&aol, g_aol);

    cudaFuncSetAttribute(gemm_f16,
                         cudaFuncAttributeMaxDynamicSharedMemorySize, G_SMEM_BYTES);
    cudaFuncSetAttribute(attn_tc,
                         cudaFuncAttributeMaxDynamicSharedMemorySize, A_SMEM_BYTES);

    const int M = BATCH * SEQ;  // 4096

    // 0) One-launch prep: split x; round weights
    prep_all<<<592, 256>>>(x, W_qkv, W_out, xh, xl, wqh, woh);

    // 1) QKV projection -> split fp16 qkv
    {
        dim3 grid(QKVD / 128, M / 128);
        gemm_f16<<<grid, 256, G_SMEM_BYTES>>>(M, QKVD, DIM, xh, xl, wqh,
                                              b_qkv, nullptr, qkvh, qkvl);
    }
    // 2) Attention -> split fp16 aout
    {
        dim3 grid(SEQ / 128, HEADS, BATCH);
        attn_tc<<<grid, 256, A_SMEM_BYTES>>>(qkvh, qkvl, aoh, aol);
    }
    // 3) Output projection -> fp32 out
    {
        dim3 grid(DIM / 128, M / 128);
        gemm_f16<<<grid, 256, G_SMEM_BYTES>>>(M, DIM, DIM, aoh, aol, woh,
                                              b_out, out, nullptr, nullptr);
    }
}

// round 14
// speedup vs baseline: 2.3326x; 1.4569x over previous
#include <cuda_runtime.h>
#include <cuda_fp16.h>
#include <math.h>
#include <stdint.h>

// Problem constants
#define BATCH 2
#define SEQ   2048
#define DIM   1024
#define HEADS 16
#define HD    64
#define QKVD  3072   // 3*DIM

// ---------------------------------------------------------------------------
// Global scratch (alloc-free rule). Single fp16 everywhere (R14):
// calibrated fp16 rounding events RSS to ~5e-4 total, under the 1e-3 gate.
// ---------------------------------------------------------------------------
__device__ __half g_xh [(size_t)BATCH * SEQ * DIM];
__device__ __half g_wqh[(size_t)QKVD * DIM];
__device__ __half g_woh[(size_t)DIM * DIM];
__device__ __half g_qkvh[(size_t)BATCH * SEQ * QKVD];
__device__ __half g_aoh[(size_t)BATCH * SEQ * DIM];

// ============================================================================
// Helpers (generic PTX, compute_103-safe)
// ============================================================================
__device__ __forceinline__ uint32_t smem_u32(const void* p) {
    uint32_t a;
    asm("{ .reg .u64 t; cvta.to.shared.u64 t, %1; cvt.u32.u64 %0, t; }"
        : "=r"(a) : "l"(p));
    return a;
}
__device__ __forceinline__ void ldsm_x4(uint32_t& r0, uint32_t& r1,
                                        uint32_t& r2, uint32_t& r3,
                                        uint32_t addr) {
    asm volatile("ldmatrix.sync.aligned.m8n8.x4.shared.b16 {%0,%1,%2,%3}, [%4];"
                 : "=r"(r0), "=r"(r1), "=r"(r2), "=r"(r3) : "r"(addr));
}
__device__ __forceinline__ void mma_f16(float* d, const uint32_t* a,
                                        const uint32_t* b) {
    asm volatile(
        "mma.sync.aligned.m16n8k16.row.col.f32.f16.f16.f32 "
        "{%0,%1,%2,%3}, {%4,%5,%6,%7}, {%8,%9}, {%0,%1,%2,%3};"
        : "+f"(d[0]), "+f"(d[1]), "+f"(d[2]), "+f"(d[3])
        : "r"(a[0]), "r"(a[1]), "r"(a[2]), "r"(a[3]), "r"(b[0]), "r"(b[1]));
}
__device__ __forceinline__ uint32_t pack2h(float x, float y) {
    __half2 h = __floats2half2_rn(x, y);
    return *(uint32_t*)&h;
}
__device__ __forceinline__ void cp16(uint32_t smem, const void* gmem) {
    asm volatile("cp.async.cg.shared.global [%0], [%1], 16;"
                 :: "r"(smem), "l"(gmem));
}
#define CP_COMMIT() asm volatile("cp.async.commit_group;" ::: "memory")
#define CP_WAIT(n)  asm volatile("cp.async.wait_group %0;" :: "n"(n) : "memory")

// ============================================================================
// prep_all: one launch — round x and both weights to fp16.
// ============================================================================
#define XN4  (BATCH * SEQ * DIM / 4)
#define WQ4  (QKVD * DIM / 4)
#define WO4  (DIM * DIM / 4)

__global__ void prep_all(const float* __restrict__ x,
                         const float* __restrict__ wq,
                         const float* __restrict__ wo,
                         __half* __restrict__ xh,
                         __half* __restrict__ wqh, __half* __restrict__ woh) {
    const int stride = gridDim.x * blockDim.x;
    const int base = blockIdx.x * blockDim.x + threadIdx.x;
    for (int i = base; i < XN4; i += stride) {
        float4 v = ((const float4*)x)[i];
        uint2 h;
        h.x = pack2h(v.x, v.y);
        h.y = pack2h(v.z, v.w);
        ((uint2*)xh)[i] = h;
    }
    for (int i = base; i < WQ4; i += stride) {
        float4 v = ((const float4*)wq)[i];
        uint2 h;
        h.x = pack2h(v.x, v.y);
        h.y = pack2h(v.z, v.w);
        ((uint2*)wqh)[i] = h;
    }
    for (int i = base; i < WO4; i += stride) {
        float4 v = ((const float4*)wo)[i];
        uint2 h;
        h.x = pack2h(v.x, v.y);
        h.y = pack2h(v.z, v.w);
        ((uint2*)woh)[i] = h;
    }
}

// ============================================================================
// fp16 GEMM:  C = A @ B^T + bias   (single product)
// CTA tile 128x128, K-chunk 64, 2-stage cp.async, 8 warps (4m x 2n),
// warp tile 32x64, 2 CTAs/SM.
// ============================================================================
#define GKC    64
#define GPITCH 72
#define GA_TILE (128 * GPITCH * 2)
#define GB_TILE (128 * GPITCH * 2)
#define GSTAGE_B (GA_TILE + GB_TILE)        // 36864
#define G_SMEM_BYTES (2 * GSTAGE_B)         // 73728

__global__ __launch_bounds__(256, 2) void gemm_f16(
    int M, int N_, int K,
    const __half* __restrict__ Ah,
    const __half* __restrict__ Bh,
    const float* __restrict__ bias,
    float* __restrict__ C,
    __half* __restrict__ Ch)
{
    extern __shared__ __align__(16) char sm[];
    const uint32_t sb0 = smem_u32(sm);

    const int tid = threadIdx.x;
    const int wid = tid >> 5;
    const int lane = tid & 31;
    const int n0 = blockIdx.x * 128;
    const int m0 = blockIdx.y * 128;
    const int warp_m = wid & 3;
    const int warp_n = wid >> 2;

    float acc[2][8][4];
#pragma unroll
    for (int mt = 0; mt < 2; mt++)
#pragma unroll
        for (int nt = 0; nt < 8; nt++)
#pragma unroll
            for (int r = 0; r < 4; r++) acc[mt][nt][r] = 0.0f;

    const int a_row = warp_m * 32 + (lane & 7) + ((lane >> 3) & 1) * 8;
    const int a_kof = ((lane >> 4) & 1) * 8;
    const int b_row = warp_n * 64 + (lane & 7) + ((lane >> 4) & 1) * 8;
    const int b_kof = ((lane >> 3) & 1) * 8;

    const int nchunk = K / GKC;

    auto issue_chunk = [&](int ic, int s) {
        const uint32_t sb = sb0 + (uint32_t)s * GSTAGE_B;
        const int kc = ic * GKC;
#pragma unroll
        for (int i = 0; i < 4; i++) {
            const int id = tid + 256 * i;
            const int row = id >> 3;
            const int c8 = (id & 7) * 8;
            const uint32_t so = (uint32_t)(row * GPITCH + c8) * 2;
            const size_t ga = (size_t)(m0 + row) * K + kc + c8;
            const size_t gb = (size_t)(n0 + row) * K + kc + c8;
            cp16(sb + so,           Ah + ga);
            cp16(sb + GA_TILE + so, Bh + gb);
        }
    };

    issue_chunk(0, 0); CP_COMMIT();

    for (int ic = 0; ic < nchunk; ic++) {
        if (ic + 1 < nchunk) {
            issue_chunk(ic + 1, (ic + 1) & 1); CP_COMMIT();
            CP_WAIT(1);
        } else {
            CP_WAIT(0);
        }
        __syncthreads();

        const uint32_t sb  = sb0 + (uint32_t)(ic & 1) * GSTAGE_B;
        const uint32_t sAh = sb;
        const uint32_t sBh = sb + GA_TILE;

#pragma unroll
        for (int ks = 0; ks < 4; ks++) {
            const int k16 = ks * 16;
            uint32_t ah[2][4];
#pragma unroll
            for (int mt = 0; mt < 2; mt++) {
                const uint32_t aoff =
                    (uint32_t)((a_row + mt * 16) * GPITCH + k16 + a_kof) * 2;
                ldsm_x4(ah[mt][0], ah[mt][1], ah[mt][2], ah[mt][3], sAh + aoff);
            }
            uint32_t bh[8][2];
#pragma unroll
            for (int ntp = 0; ntp < 4; ntp++) {
                const uint32_t boff =
                    (uint32_t)((b_row + ntp * 16) * GPITCH + k16 + b_kof) * 2;
                ldsm_x4(bh[2 * ntp][0], bh[2 * ntp][1],
                        bh[2 * ntp + 1][0], bh[2 * ntp + 1][1], sBh + boff);
            }
#pragma unroll
            for (int mt = 0; mt < 2; mt++)
#pragma unroll
                for (int nt = 0; nt < 8; nt++)
                    mma_f16(acc[mt][nt], ah[mt], bh[nt]);
        }
        __syncthreads();
    }

    // Epilogue
    const int er0 = m0 + warp_m * 32 + (lane >> 2);
    const int ec0 = n0 + warp_n * 64 + (lane & 3) * 2;
#pragma unroll
    for (int mt = 0; mt < 2; mt++) {
#pragma unroll
        for (int nt = 0; nt < 8; nt++) {
            const int col = ec0 + nt * 8;
            const float bx = bias[col], by = bias[col + 1];
            const size_t o0 = (size_t)(er0 + mt * 16) * N_ + col;
            const size_t o1 = (size_t)(er0 + mt * 16 + 8) * N_ + col;
            const float c00 = acc[mt][nt][0] + bx, c01 = acc[mt][nt][1] + by;
            const float c10 = acc[mt][nt][2] + bx, c11 = acc[mt][nt][3] + by;
            if (C) {
                *(float2*)(C + o0) = make_float2(c00, c01);
                *(float2*)(C + o1) = make_float2(c10, c11);
            } else {
                *(uint32_t*)(Ch + o0) = pack2h(c00, c01);
                *(uint32_t*)(Ch + o1) = pack2h(c10, c11);
            }
        }
    }
}

// ============================================================================
// Flash attention, tensor cores, full fp16 operands (single product per GEMM).
// K double-buffered cp.async; V register-prefetch pipeline.
// smem: Qh [128][72]; Kh x2 [64][72]; Vth [64][72]
// ============================================================================
#define APITCH 72
#define A_QTILE (128 * APITCH * 2)     // 18432
#define A_KBUF  (64 * APITCH * 2)      //  9216
#define A_SMEM_BYTES (A_QTILE + 3 * A_KBUF)   // 46080

__global__ __launch_bounds__(256, 1) void attn_tc(
    const __half* __restrict__ qkvh,
    __half* __restrict__ aoh)
{
    extern __shared__ __align__(16) char smema[];
    const uint32_t sQh  = smem_u32(smema);
    const uint32_t sKh0 = sQh + A_QTILE;
    const uint32_t sKh1 = sKh0 + A_KBUF;
    const uint32_t sVth = sKh1 + A_KBUF;
    __half* pVth = (__half*)(smema + A_QTILE + 2 * A_KBUF);

    const int qt = gridDim.x - 1 - blockIdx.x;   // heavy tiles first
    const int h  = blockIdx.y;
    const int b  = blockIdx.z;
    const int tid = threadIdx.x;
    const int wid = tid >> 5;
    const int lane = tid & 31;

    const size_t bN = (size_t)b * SEQ;
    const int qcol = h * HD;
    const int kcol = DIM + h * HD;
    const int vcol = 2 * DIM + h * HD;
    const int ntiles = (qt + 1) * 2;

    const int vrr = tid >> 2;
    const int vd0 = (tid & 3) * 16;

    auto issue_k = [&](int kt, uint32_t kbuf) {
        const int kb = kt * 64;
#pragma unroll
        for (int i = 0; i < 2; i++) {
            const int id = tid + 256 * i;
            const int row = id >> 3;
            const int c8 = (id & 7) * 8;
            const uint32_t so = (uint32_t)(row * APITCH + c8) * 2;
            const size_t g = (bN + kb + row) * QKVD + kcol + c8;
            cp16(kbuf + so, qkvh + g);
        }
    };

    // ---- Q tile (cp.async) + K(0) (cp.async) + V(0) (register prefetch) ----
#pragma unroll
    for (int i = 0; i < 2; i++) {
        const int id = tid + 256 * i;
        const int row = id >> 2;             // 128 rows, 4 col-groups
        const int c8 = (id & 3) * 16;
        const uint32_t so = (uint32_t)(row * APITCH + c8) * 2;
        const size_t g = (bN + qt * 128 + row) * QKVD + qcol + c8;
        cp16(sQh + so,      qkvh + g);
        cp16(sQh + so + 16, qkvh + g + 8);
    }
    CP_COMMIT();
    issue_k(0, sKh0);
    CP_COMMIT();

    uint4 va, vb;
    {
        const size_t g = (bN + vrr) * QKVD + vcol + vd0;
        va = *(const uint4*)(qkvh + g);
        vb = *(const uint4*)(qkvh + g + 8);
    }

    CP_WAIT(1);
    __syncthreads();

    // ---- Hoist Q fragments ----
    const int a_row = wid * 16 + (lane & 7) + ((lane >> 3) & 1) * 8;
    const int a_kof = ((lane >> 4) & 1) * 8;
    uint32_t qh[4][4];
#pragma unroll
    for (int ks = 0; ks < 4; ks++) {
        const uint32_t off = (uint32_t)(a_row * APITCH + ks * 16 + a_kof) * 2;
        ldsm_x4(qh[ks][0], qh[ks][1], qh[ks][2], qh[ks][3], sQh + off);
    }

    const int b_row = (lane & 7) + ((lane >> 4) & 1) * 8;
    const int b_kof = ((lane >> 3) & 1) * 8;

    float o[8][4];
#pragma unroll
    for (int nt = 0; nt < 8; nt++)
#pragma unroll
        for (int r = 0; r < 4; r++) o[nt][r] = 0.0f;
    float m0 = -1e30f, m1 = -1e30f, l0 = 0.0f, l1 = 0.0f;

    const float scale = 0.125f;
    const int row_lo = qt * 128 + wid * 16 + (lane >> 2);
    const int row_hi = row_lo + 8;

    for (int kt = 0; kt < ntiles; kt++) {
        const int kb = kt * 64;
        const uint32_t sKcur = (kt & 1) ? sKh1 : sKh0;
        const bool have_next = (kt + 1 < ntiles);

        if (have_next) {
            issue_k(kt + 1, (kt & 1) ? sKh0 : sKh1);
            CP_COMMIT();
        }

        // Store V(kt) (prefetched) to smem transposed
        {
            union { uint4 q; __half e[8]; } u0, u1;
            u0.q = va; u1.q = vb;
#pragma unroll
            for (int e = 0; e < 8; e++) {
                pVth[(vd0 + e) * APITCH + vrr]     = u0.e[e];
                pVth[(vd0 + 8 + e) * APITCH + vrr] = u1.e[e];
            }
        }
        // Prefetch V(kt+1)
        uint4 va2 = va, vb2 = vb;
        if (have_next) {
            const size_t g = (bN + kb + 64 + vrr) * QKVD + vcol + vd0;
            va2 = *(const uint4*)(qkvh + g);
            vb2 = *(const uint4*)(qkvh + g + 8);
        }

        if (have_next) { CP_WAIT(1); } else { CP_WAIT(0); }
        __syncthreads();

        // ---- S = Q @ K^T (single product pass) ----
        float s[8][4];
#pragma unroll
        for (int nt = 0; nt < 8; nt++)
#pragma unroll
            for (int r = 0; r < 4; r++) s[nt][r] = 0.0f;

#pragma unroll
        for (int ks = 0; ks < 4; ks++) {
            uint32_t kh[8][2];
#pragma unroll
            for (int ntp = 0; ntp < 4; ntp++) {
                const uint32_t off =
                    (uint32_t)((ntp * 16 + b_row) * APITCH + ks * 16 + b_kof) * 2;
                ldsm_x4(kh[2 * ntp][0], kh[2 * ntp][1],
                        kh[2 * ntp + 1][0], kh[2 * ntp + 1][1], sKcur + off);
            }
#pragma unroll
            for (int nt = 0; nt < 8; nt++) mma_f16(s[nt], qh[ks], kh[nt]);
        }

        // ---- Scale + causal mask ----
        const bool full = (kb + 63) <= qt * 128;
        if (full) {
#pragma unroll
            for (int nt = 0; nt < 8; nt++)
#pragma unroll
                for (int r = 0; r < 4; r++) s[nt][r] *= scale;
        } else {
#pragma unroll
            for (int nt = 0; nt < 8; nt++) {
                const int col = kb + nt * 8 + (lane & 3) * 2;
                s[nt][0] = (col     <= row_lo) ? s[nt][0] * scale : -1e30f;
                s[nt][1] = (col + 1 <= row_lo) ? s[nt][1] * scale : -1e30f;
                s[nt][2] = (col     <= row_hi) ? s[nt][2] * scale : -1e30f;
                s[nt][3] = (col + 1 <= row_hi) ? s[nt][3] * scale : -1e30f;
            }
        }

        // ---- Online softmax ----
        float tm0 = -1e30f, tm1 = -1e30f;
#pragma unroll
        for (int nt = 0; nt < 8; nt++) {
            tm0 = fmaxf(tm0, fmaxf(s[nt][0], s[nt][1]));
            tm1 = fmaxf(tm1, fmaxf(s[nt][2], s[nt][3]));
        }
        tm0 = fmaxf(tm0, __shfl_xor_sync(0xffffffffu, tm0, 1));
        tm0 = fmaxf(tm0, __shfl_xor_sync(0xffffffffu, tm0, 2));
        tm1 = fmaxf(tm1, __shfl_xor_sync(0xffffffffu, tm1, 1));
        tm1 = fmaxf(tm1, __shfl_xor_sync(0xffffffffu, tm1, 2));

        const float nm0 = fmaxf(m0, tm0);
        const float nm1 = fmaxf(m1, tm1);
        const float corr0 = __expf(m0 - nm0);
        const float corr1 = __expf(m1 - nm1);

        float ps0 = 0.0f, ps1 = 0.0f;
#pragma unroll
        for (int nt = 0; nt < 8; nt++) {
            s[nt][0] = __expf(s[nt][0] - nm0); ps0 += s[nt][0];
            s[nt][1] = __expf(s[nt][1] - nm0); ps0 += s[nt][1];
            s[nt][2] = __expf(s[nt][2] - nm1); ps1 += s[nt][2];
            s[nt][3] = __expf(s[nt][3] - nm1); ps1 += s[nt][3];
        }
        ps0 += __shfl_xor_sync(0xffffffffu, ps0, 1);
        ps0 += __shfl_xor_sync(0xffffffffu, ps0, 2);
        ps1 += __shfl_xor_sync(0xffffffffu, ps1, 1);
        ps1 += __shfl_xor_sync(0xffffffffu, ps1, 2);

        l0 = l0 * corr0 + ps0; m0 = nm0;
        l1 = l1 * corr1 + ps1; m1 = nm1;
#pragma unroll
        for (int nt = 0; nt < 8; nt++) {
            o[nt][0] *= corr0; o[nt][1] *= corr0;
            o[nt][2] *= corr1; o[nt][3] *= corr1;
        }

        // ---- O += P @ V (P single fp16, one product pass) ----
        uint32_t pa[4][4], vh[4][8][2];
#pragma unroll
        for (int ks = 0; ks < 4; ks++) {
            const int j = 2 * ks;
            pa[ks][0] = pack2h(s[j][0],     s[j][1]);
            pa[ks][1] = pack2h(s[j][2],     s[j][3]);
            pa[ks][2] = pack2h(s[j + 1][0], s[j + 1][1]);
            pa[ks][3] = pack2h(s[j + 1][2], s[j + 1][3]);
#pragma unroll
            for (int ntp = 0; ntp < 4; ntp++) {
                const uint32_t off =
                    (uint32_t)((ntp * 16 + b_row) * APITCH + ks * 16 + b_kof) * 2;
                ldsm_x4(vh[ks][2 * ntp][0], vh[ks][2 * ntp][1],
                        vh[ks][2 * ntp + 1][0], vh[ks][2 * ntp + 1][1], sVth + off);
            }
        }
#pragma unroll
        for (int ks = 0; ks < 4; ks++)
#pragma unroll
            for (int nt = 0; nt < 8; nt++) mma_f16(o[nt], pa[ks], vh[ks][nt]);
        __syncthreads();   // protects Vth + K buffer reuse next iteration

        va = va2; vb = vb2;
    }

    // ---- Epilogue: normalize + fp16 store ----
    const float inv0 = 1.0f / l0;
    const float inv1 = 1.0f / l1;
#pragma unroll
    for (int nt = 0; nt < 8; nt++) {
        const int col = h * HD + nt * 8 + (lane & 3) * 2;
        const size_t o0 = (bN + row_lo) * DIM + col;
        const size_t o1 = (bN + row_hi) * DIM + col;
        *(uint32_t*)(aoh + o0) = pack2h(o[nt][0] * inv0, o[nt][1] * inv0);
        *(uint32_t*)(aoh + o1) = pack2h(o[nt][2] * inv1, o[nt][3] * inv1);
    }
}

// ---------------------------------------------------------------------------
extern "C" void kernel_launch(void* const* d_in, const int* in_sizes, int n_in,
                              void* d_out, int out_size)
{
    const float* x     = (const float*)d_in[0];
    const float* W_qkv = (const float*)d_in[1];
    const float* b_qkv = (const float*)d_in[2];
    const float* W_out = (const float*)d_in[3];
    const float* b_out = (const float*)d_in[4];
    float* out = (float*)d_out;

    __half *xh, *wqh, *woh, *qkvh, *aoh;
    cudaGetSymbolAddress((void**)&xh,  g_xh);
    cudaGetSymbolAddress((void**)&wqh, g_wqh);
    cudaGetSymbolAddress((void**)&woh, g_woh);
    cudaGetSymbolAddress((void**)&qkvh, g_qkvh);
    cudaGetSymbolAddress((void**)&aoh, g_aoh);

    cudaFuncSetAttribute(gemm_f16,
                         cudaFuncAttributeMaxDynamicSharedMemorySize, G_SMEM_BYTES);
    cudaFuncSetAttribute(attn_tc,
                         cudaFuncAttributeMaxDynamicSharedMemorySize, A_SMEM_BYTES);

    const int M = BATCH * SEQ;  // 4096

    // 0) One-launch prep: round x + weights to fp16
    prep_all<<<592, 256>>>(x, W_qkv, W_out, xh, wqh, woh);

    // 1) QKV projection -> fp16 qkv
    {
        dim3 grid(QKVD / 128, M / 128);
        gemm_f16<<<grid, 256, G_SMEM_BYTES>>>(M, QKVD, DIM, xh, wqh,
                                              b_qkv, nullptr, qkvh);
    }
    // 2) Attention -> fp16 aout
    {
        dim3 grid(SEQ / 128, HEADS, BATCH);
        attn_tc<<<grid, 256, A_SMEM_BYTES>>>(qkvh, aoh);
    }
    // 3) Output projection -> fp32 out
    {
        dim3 grid(DIM / 128, M / 128);
        gemm_f16<<<grid, 256, G_SMEM_BYTES>>>(M, DIM, DIM, aoh, woh,
                                              b_out, out, nullptr);
    }
}

// round 15
// speedup vs baseline: 2.3748x; 1.0181x over previous
#include <cuda_runtime.h>
#include <cuda_fp16.h>
#include <math.h>
#include <stdint.h>

// Problem constants
#define BATCH 2
#define SEQ   2048
#define DIM   1024
#define HEADS 16
#define HD    64
#define QKVD  3072   // 3*DIM

// ---------------------------------------------------------------------------
// Global scratch (alloc-free rule). Single fp16 everywhere.
// ---------------------------------------------------------------------------
__device__ __half g_xh [(size_t)BATCH * SEQ * DIM];
__device__ __half g_wqh[(size_t)QKVD * DIM];
__device__ __half g_woh[(size_t)DIM * DIM];
__device__ __half g_qkvh[(size_t)BATCH * SEQ * QKVD];
__device__ __half g_aoh[(size_t)BATCH * SEQ * DIM];

// ============================================================================
// Helpers (generic PTX, compute_103-safe)
// ============================================================================
__device__ __forceinline__ uint32_t smem_u32(const void* p) {
    uint32_t a;
    asm("{ .reg .u64 t; cvta.to.shared.u64 t, %1; cvt.u32.u64 %0, t; }"
        : "=r"(a) : "l"(p));
    return a;
}
__device__ __forceinline__ void ldsm_x4(uint32_t& r0, uint32_t& r1,
                                        uint32_t& r2, uint32_t& r3,
                                        uint32_t addr) {
    asm volatile("ldmatrix.sync.aligned.m8n8.x4.shared.b16 {%0,%1,%2,%3}, [%4];"
                 : "=r"(r0), "=r"(r1), "=r"(r2), "=r"(r3) : "r"(addr));
}
__device__ __forceinline__ void mma_f16(float* d, const uint32_t* a,
                                        const uint32_t* b) {
    asm volatile(
        "mma.sync.aligned.m16n8k16.row.col.f32.f16.f16.f32 "
        "{%0,%1,%2,%3}, {%4,%5,%6,%7}, {%8,%9}, {%0,%1,%2,%3};"
        : "+f"(d[0]), "+f"(d[1]), "+f"(d[2]), "+f"(d[3])
        : "r"(a[0]), "r"(a[1]), "r"(a[2]), "r"(a[3]), "r"(b[0]), "r"(b[1]));
}
__device__ __forceinline__ uint32_t pack2h(float x, float y) {
    __half2 h = __floats2half2_rn(x, y);
    return *(uint32_t*)&h;
}
__device__ __forceinline__ void cp16(uint32_t smem, const void* gmem) {
    asm volatile("cp.async.cg.shared.global [%0], [%1], 16;"
                 :: "r"(smem), "l"(gmem));
}
#define CP_COMMIT() asm volatile("cp.async.commit_group;" ::: "memory")
#define CP_WAIT(n)  asm volatile("cp.async.wait_group %0;" :: "n"(n) : "memory")

// ============================================================================
// prep_all: one launch — round x and both weights to fp16.
// ============================================================================
#define XN4  (BATCH * SEQ * DIM / 4)
#define WQ4  (QKVD * DIM / 4)
#define WO4  (DIM * DIM / 4)

__global__ void prep_all(const float* __restrict__ x,
                         const float* __restrict__ wq,
                         const float* __restrict__ wo,
                         __half* __restrict__ xh,
                         __half* __restrict__ wqh, __half* __restrict__ woh) {
    const int stride = gridDim.x * blockDim.x;
    const int base = blockIdx.x * blockDim.x + threadIdx.x;
    for (int i = base; i < XN4; i += stride) {
        float4 v = ((const float4*)x)[i];
        uint2 h;
        h.x = pack2h(v.x, v.y);
        h.y = pack2h(v.z, v.w);
        ((uint2*)xh)[i] = h;
    }
    for (int i = base; i < WQ4; i += stride) {
        float4 v = ((const float4*)wq)[i];
        uint2 h;
        h.x = pack2h(v.x, v.y);
        h.y = pack2h(v.z, v.w);
        ((uint2*)wqh)[i] = h;
    }
    for (int i = base; i < WO4; i += stride) {
        float4 v = ((const float4*)wo)[i];
        uint2 h;
        h.x = pack2h(v.x, v.y);
        h.y = pack2h(v.z, v.w);
        ((uint2*)woh)[i] = h;
    }
}

// ============================================================================
// fp16 GEMM:  C = A @ B^T + bias   (single product; frozen — at roofline)
// ============================================================================
#define GKC    64
#define GPITCH 72
#define GA_TILE (128 * GPITCH * 2)
#define GB_TILE (128 * GPITCH * 2)
#define GSTAGE_B (GA_TILE + GB_TILE)
#define G_SMEM_BYTES (2 * GSTAGE_B)

__global__ __launch_bounds__(256, 2) void gemm_f16(
    int M, int N_, int K,
    const __half* __restrict__ Ah,
    const __half* __restrict__ Bh,
    const float* __restrict__ bias,
    float* __restrict__ C,
    __half* __restrict__ Ch)
{
    extern __shared__ __align__(16) char sm[];
    const uint32_t sb0 = smem_u32(sm);

    const int tid = threadIdx.x;
    const int wid = tid >> 5;
    const int lane = tid & 31;
    const int n0 = blockIdx.x * 128;
    const int m0 = blockIdx.y * 128;
    const int warp_m = wid & 3;
    const int warp_n = wid >> 2;

    float acc[2][8][4];
#pragma unroll
    for (int mt = 0; mt < 2; mt++)
#pragma unroll
        for (int nt = 0; nt < 8; nt++)
#pragma unroll
            for (int r = 0; r < 4; r++) acc[mt][nt][r] = 0.0f;

    const int a_row = warp_m * 32 + (lane & 7) + ((lane >> 3) & 1) * 8;
    const int a_kof = ((lane >> 4) & 1) * 8;
    const int b_row = warp_n * 64 + (lane & 7) + ((lane >> 4) & 1) * 8;
    const int b_kof = ((lane >> 3) & 1) * 8;

    const int nchunk = K / GKC;

    auto issue_chunk = [&](int ic, int s) {
        const uint32_t sb = sb0 + (uint32_t)s * GSTAGE_B;
        const int kc = ic * GKC;
#pragma unroll
        for (int i = 0; i < 4; i++) {
            const int id = tid + 256 * i;
            const int row = id >> 3;
            const int c8 = (id & 7) * 8;
            const uint32_t so = (uint32_t)(row * GPITCH + c8) * 2;
            const size_t ga = (size_t)(m0 + row) * K + kc + c8;
            const size_t gb = (size_t)(n0 + row) * K + kc + c8;
            cp16(sb + so,           Ah + ga);
            cp16(sb + GA_TILE + so, Bh + gb);
        }
    };

    issue_chunk(0, 0); CP_COMMIT();

    for (int ic = 0; ic < nchunk; ic++) {
        if (ic + 1 < nchunk) {
            issue_chunk(ic + 1, (ic + 1) & 1); CP_COMMIT();
            CP_WAIT(1);
        } else {
            CP_WAIT(0);
        }
        __syncthreads();

        const uint32_t sb  = sb0 + (uint32_t)(ic & 1) * GSTAGE_B;
        const uint32_t sAh = sb;
        const uint32_t sBh = sb + GA_TILE;

#pragma unroll
        for (int ks = 0; ks < 4; ks++) {
            const int k16 = ks * 16;
            uint32_t ah[2][4];
#pragma unroll
            for (int mt = 0; mt < 2; mt++) {
                const uint32_t aoff =
                    (uint32_t)((a_row + mt * 16) * GPITCH + k16 + a_kof) * 2;
                ldsm_x4(ah[mt][0], ah[mt][1], ah[mt][2], ah[mt][3], sAh + aoff);
            }
            uint32_t bh[8][2];
#pragma unroll
            for (int ntp = 0; ntp < 4; ntp++) {
                const uint32_t boff =
                    (uint32_t)((b_row + ntp * 16) * GPITCH + k16 + b_kof) * 2;
                ldsm_x4(bh[2 * ntp][0], bh[2 * ntp][1],
                        bh[2 * ntp + 1][0], bh[2 * ntp + 1][1], sBh + boff);
            }
#pragma unroll
            for (int mt = 0; mt < 2; mt++)
#pragma unroll
                for (int nt = 0; nt < 8; nt++)
                    mma_f16(acc[mt][nt], ah[mt], bh[nt]);
        }
        __syncthreads();
    }

    // Epilogue
    const int er0 = m0 + warp_m * 32 + (lane >> 2);
    const int ec0 = n0 + warp_n * 64 + (lane & 3) * 2;
#pragma unroll
    for (int mt = 0; mt < 2; mt++) {
#pragma unroll
        for (int nt = 0; nt < 8; nt++) {
            const int col = ec0 + nt * 8;
            const float bx = bias[col], by = bias[col + 1];
            const size_t o0 = (size_t)(er0 + mt * 16) * N_ + col;
            const size_t o1 = (size_t)(er0 + mt * 16 + 8) * N_ + col;
            const float c00 = acc[mt][nt][0] + bx, c01 = acc[mt][nt][1] + by;
            const float c10 = acc[mt][nt][2] + bx, c11 = acc[mt][nt][3] + by;
            if (C) {
                *(float2*)(C + o0) = make_float2(c00, c01);
                *(float2*)(C + o1) = make_float2(c10, c11);
            } else {
                *(uint32_t*)(Ch + o0) = pack2h(c00, c01);
                *(uint32_t*)(Ch + o1) = pack2h(c10, c11);
            }
        }
    }
}

// ============================================================================
// Flash attention, tensor cores, full fp16 operands.
// R15: 2 CTAs/SM (register-trimmed: V frags + P packed per k-step inside
// the PV pass instead of prefetched in bulk).
// smem: Qh [128][72]; Kh x2 [64][72]; Vth [64][72]
// ============================================================================
#define APITCH 72
#define A_QTILE (128 * APITCH * 2)     // 18432
#define A_KBUF  (64 * APITCH * 2)      //  9216
#define A_SMEM_BYTES (A_QTILE + 3 * A_KBUF)   // 46080

__global__ __launch_bounds__(256, 2) void attn_tc(
    const __half* __restrict__ qkvh,
    __half* __restrict__ aoh)
{
    extern __shared__ __align__(16) char smema[];
    const uint32_t sQh  = smem_u32(smema);
    const uint32_t sKh0 = sQh + A_QTILE;
    const uint32_t sKh1 = sKh0 + A_KBUF;
    const uint32_t sVth = sKh1 + A_KBUF;
    __half* pVth = (__half*)(smema + A_QTILE + 2 * A_KBUF);

    const int qt = gridDim.x - 1 - blockIdx.x;   // heavy tiles first
    const int h  = blockIdx.y;
    const int b  = blockIdx.z;
    const int tid = threadIdx.x;
    const int wid = tid >> 5;
    const int lane = tid & 31;

    const size_t bN = (size_t)b * SEQ;
    const int qcol = h * HD;
    const int kcol = DIM + h * HD;
    const int vcol = 2 * DIM + h * HD;
    const int ntiles = (qt + 1) * 2;

    const int vrr = tid >> 2;
    const int vd0 = (tid & 3) * 16;

    auto issue_k = [&](int kt, uint32_t kbuf) {
        const int kb = kt * 64;
#pragma unroll
        for (int i = 0; i < 2; i++) {
            const int id = tid + 256 * i;
            const int row = id >> 3;
            const int c8 = (id & 7) * 8;
            const uint32_t so = (uint32_t)(row * APITCH + c8) * 2;
            const size_t g = (bN + kb + row) * QKVD + kcol + c8;
            cp16(kbuf + so, qkvh + g);
        }
    };

    // ---- Q tile (cp.async) + K(0) (cp.async) + V(0) (register prefetch) ----
#pragma unroll
    for (int i = 0; i < 2; i++) {
        const int id = tid + 256 * i;
        const int row = id >> 2;
        const int c8 = (id & 3) * 16;
        const uint32_t so = (uint32_t)(row * APITCH + c8) * 2;
        const size_t g = (bN + qt * 128 + row) * QKVD + qcol + c8;
        cp16(sQh + so,      qkvh + g);
        cp16(sQh + so + 16, qkvh + g + 8);
    }
    CP_COMMIT();
    issue_k(0, sKh0);
    CP_COMMIT();

    uint4 va, vb;
    {
        const size_t g = (bN + vrr) * QKVD + vcol + vd0;
        va = *(const uint4*)(qkvh + g);
        vb = *(const uint4*)(qkvh + g + 8);
    }

    CP_WAIT(1);
    __syncthreads();

    // ---- Hoist Q fragments ----
    const int a_row = wid * 16 + (lane & 7) + ((lane >> 3) & 1) * 8;
    const int a_kof = ((lane >> 4) & 1) * 8;
    uint32_t qh[4][4];
#pragma unroll
    for (int ks = 0; ks < 4; ks++) {
        const uint32_t off = (uint32_t)(a_row * APITCH + ks * 16 + a_kof) * 2;
        ldsm_x4(qh[ks][0], qh[ks][1], qh[ks][2], qh[ks][3], sQh + off);
    }

    const int b_row = (lane & 7) + ((lane >> 4) & 1) * 8;
    const int b_kof = ((lane >> 3) & 1) * 8;

    float o[8][4];
#pragma unroll
    for (int nt = 0; nt < 8; nt++)
#pragma unroll
        for (int r = 0; r < 4; r++) o[nt][r] = 0.0f;
    float m0 = -1e30f, m1 = -1e30f, l0 = 0.0f, l1 = 0.0f;

    const float scale = 0.125f;
    const int row_lo = qt * 128 + wid * 16 + (lane >> 2);
    const int row_hi = row_lo + 8;

    for (int kt = 0; kt < ntiles; kt++) {
        const int kb = kt * 64;
        const uint32_t sKcur = (kt & 1) ? sKh1 : sKh0;
        const bool have_next = (kt + 1 < ntiles);

        if (have_next) {
            issue_k(kt + 1, (kt & 1) ? sKh0 : sKh1);
            CP_COMMIT();
        }

        // Store V(kt) (prefetched) to smem transposed
        {
            union { uint4 q; __half e[8]; } u0, u1;
            u0.q = va; u1.q = vb;
#pragma unroll
            for (int e = 0; e < 8; e++) {
                pVth[(vd0 + e) * APITCH + vrr]     = u0.e[e];
                pVth[(vd0 + 8 + e) * APITCH + vrr] = u1.e[e];
            }
        }
        // Prefetch V(kt+1)
        uint4 va2 = va, vb2 = vb;
        if (have_next) {
            const size_t g = (bN + kb + 64 + vrr) * QKVD + vcol + vd0;
            va2 = *(const uint4*)(qkvh + g);
            vb2 = *(const uint4*)(qkvh + g + 8);
        }

        if (have_next) { CP_WAIT(1); } else { CP_WAIT(0); }
        __syncthreads();

        // ---- S = Q @ K^T (single product pass) ----
        float s[8][4];
#pragma unroll
        for (int nt = 0; nt < 8; nt++)
#pragma unroll
            for (int r = 0; r < 4; r++) s[nt][r] = 0.0f;

#pragma unroll
        for (int ks = 0; ks < 4; ks++) {
            uint32_t kh[8][2];
#pragma unroll
            for (int ntp = 0; ntp < 4; ntp++) {
                const uint32_t off =
                    (uint32_t)((ntp * 16 + b_row) * APITCH + ks * 16 + b_kof) * 2;
                ldsm_x4(kh[2 * ntp][0], kh[2 * ntp][1],
                        kh[2 * ntp + 1][0], kh[2 * ntp + 1][1], sKcur + off);
            }
#pragma unroll
            for (int nt = 0; nt < 8; nt++) mma_f16(s[nt], qh[ks], kh[nt]);
        }

        // ---- Scale + causal mask ----
        const bool full = (kb + 63) <= qt * 128;
        if (full) {
#pragma unroll
            for (int nt = 0; nt < 8; nt++)
#pragma unroll
                for (int r = 0; r < 4; r++) s[nt][r] *= scale;
        } else {
#pragma unroll
            for (int nt = 0; nt < 8; nt++) {
                const int col = kb + nt * 8 + (lane & 3) * 2;
                s[nt][0] = (col     <= row_lo) ? s[nt][0] * scale : -1e30f;
                s[nt][1] = (col + 1 <= row_lo) ? s[nt][1] * scale : -1e30f;
                s[nt][2] = (col     <= row_hi) ? s[nt][2] * scale : -1e30f;
                s[nt][3] = (col + 1 <= row_hi) ? s[nt][3] * scale : -1e30f;
            }
        }

        // ---- Online softmax ----
        float tm0 = -1e30f, tm1 = -1e30f;
#pragma unroll
        for (int nt = 0; nt < 8; nt++) {
            tm0 = fmaxf(tm0, fmaxf(s[nt][0], s[nt][1]));
            tm1 = fmaxf(tm1, fmaxf(s[nt][2], s[nt][3]));
        }
        tm0 = fmaxf(tm0, __shfl_xor_sync(0xffffffffu, tm0, 1));
        tm0 = fmaxf(tm0, __shfl_xor_sync(0xffffffffu, tm0, 2));
        tm1 = fmaxf(tm1, __shfl_xor_sync(0xffffffffu, tm1, 1));
        tm1 = fmaxf(tm1, __shfl_xor_sync(0xffffffffu, tm1, 2));

        const float nm0 = fmaxf(m0, tm0);
        const float nm1 = fmaxf(m1, tm1);
        const float corr0 = __expf(m0 - nm0);
        const float corr1 = __expf(m1 - nm1);

        float ps0 = 0.0f, ps1 = 0.0f;
#pragma unroll
        for (int nt = 0; nt < 8; nt++) {
            s[nt][0] = __expf(s[nt][0] - nm0); ps0 += s[nt][0];
            s[nt][1] = __expf(s[nt][1] - nm0); ps0 += s[nt][1];
            s[nt][2] = __expf(s[nt][2] - nm1); ps1 += s[nt][2];
            s[nt][3] = __expf(s[nt][3] - nm1); ps1 += s[nt][3];
        }
        ps0 += __shfl_xor_sync(0xffffffffu, ps0, 1);
        ps0 += __shfl_xor_sync(0xffffffffu, ps0, 2);
        ps1 += __shfl_xor_sync(0xffffffffu, ps1, 1);
        ps1 += __shfl_xor_sync(0xffffffffu, ps1, 2);

        l0 = l0 * corr0 + ps0; m0 = nm0;
        l1 = l1 * corr1 + ps1; m1 = nm1;
#pragma unroll
        for (int nt = 0; nt < 8; nt++) {
            o[nt][0] *= corr0; o[nt][1] *= corr0;
            o[nt][2] *= corr1; o[nt][3] *= corr1;
        }

        // ---- O += P @ V (register-lean: pack P + load V frags per k-step) ----
#pragma unroll
        for (int ks = 0; ks < 4; ks++) {
            const int j = 2 * ks;
            uint32_t pa[4];
            pa[0] = pack2h(s[j][0],     s[j][1]);
            pa[1] = pack2h(s[j][2],     s[j][3]);
            pa[2] = pack2h(s[j + 1][0], s[j + 1][1]);
            pa[3] = pack2h(s[j + 1][2], s[j + 1][3]);
            uint32_t vh[8][2];
#pragma unroll
            for (int ntp = 0; ntp < 4; ntp++) {
                const uint32_t off =
                    (uint32_t)((ntp * 16 + b_row) * APITCH + ks * 16 + b_kof) * 2;
                ldsm_x4(vh[2 * ntp][0], vh[2 * ntp][1],
                        vh[2 * ntp + 1][0], vh[2 * ntp + 1][1], sVth + off);
            }
#pragma unroll
            for (int nt = 0; nt < 8; nt++) mma_f16(o[nt], pa, vh[nt]);
        }
        __syncthreads();   // protects Vth + K buffer reuse next iteration

        va = va2; vb = vb2;
    }

    // ---- Epilogue: normalize + fp16 store ----
    const float inv0 = 1.0f / l0;
    const float inv1 = 1.0f / l1;
#pragma unroll
    for (int nt = 0; nt < 8; nt++) {
        const int col = h * HD + nt * 8 + (lane & 3) * 2;
        const size_t o0 = (bN + row_lo) * DIM + col;
        const size_t o1 = (bN + row_hi) * DIM + col;
        *(uint32_t*)(aoh + o0) = pack2h(o[nt][0] * inv0, o[nt][1] * inv0);
        *(uint32_t*)(aoh + o1) = pack2h(o[nt][2] * inv1, o[nt][3] * inv1);
    }
}

// ---------------------------------------------------------------------------
extern "C" void kernel_launch(void* const* d_in, const int* in_sizes, int n_in,
                              void* d_out, int out_size)
{
    const float* x     = (const float*)d_in[0];
    const float* W_qkv = (const float*)d_in[1];
    const float* b_qkv = (const float*)d_in[2];
    const float* W_out = (const float*)d_in[3];
    const float* b_out = (const float*)d_in[4];
    float* out = (float*)d_out;

    __half *xh, *wqh, *woh, *qkvh, *aoh;
    cudaGetSymbolAddress((void**)&xh,  g_xh);
    cudaGetSymbolAddress((void**)&wqh, g_wqh);
    cudaGetSymbolAddress((void**)&woh, g_woh);
    cudaGetSymbolAddress((void**)&qkvh, g_qkvh);
    cudaGetSymbolAddress((void**)&aoh, g_aoh);

    cudaFuncSetAttribute(gemm_f16,
                         cudaFuncAttributeMaxDynamicSharedMemorySize, G_SMEM_BYTES);
    cudaFuncSetAttribute(attn_tc,
                         cudaFuncAttributeMaxDynamicSharedMemorySize, A_SMEM_BYTES);

    const int M = BATCH * SEQ;  // 4096

    // 0) One-launch prep: round x + weights to fp16
    prep_all<<<592, 256>>>(x, W_qkv, W_out, xh, wqh, woh);

    // 1) QKV projection -> fp16 qkv
    {
        dim3 grid(QKVD / 128, M / 128);
        gemm_f16<<<grid, 256, G_SMEM_BYTES>>>(M, QKVD, DIM, xh, wqh,
                                              b_qkv, nullptr, qkvh);
    }
    // 2) Attention -> fp16 aout
    {
        dim3 grid(SEQ / 128, HEADS, BATCH);
        attn_tc<<<grid, 256, A_SMEM_BYTES>>>(qkvh, aoh);
    }
    // 3) Output projection -> fp32 out
    {
        dim3 grid(DIM / 128, M / 128);
        gemm_f16<<<grid, 256, G_SMEM_BYTES>>>(M, DIM, DIM, aoh, woh,
                                              b_out, out, nullptr);
    }
}